// round 7
// baseline (speedup 1.0000x reference)
#include <cuda_runtime.h>
#include <cuda_bf16.h>
#include <cstdint>

#define B_   2
#define S_   2048
#define D_   1024
#define H_   16
#define DK_  64
#define DFF_ 4096
#define ROWS (B_*S_)     // 4096
#define QKV_S (3*D_)     // 3072

// ---------------- scratch (device globals; no allocations allowed) ----------
__device__ float g_bufA[ROWS*D_];      // nx -> ctx
__device__ float g_x1 [ROWS*D_];       // x after attn residual
__device__ float g_qkv[ROWS*QKV_S];    // packed q|k|v ; later reused as nx2
__device__ float g_h  [ROWS*DFF_];     // ffn hidden
// tf32-rounded weights
__device__ float g_wqkv[3*D_*D_];
__device__ float g_bqkv[3*D_];
__device__ float g_wo[D_*D_];
__device__ float g_w1[DFF_*D_], g_w2[D_*DFF_];

// ---------------- helpers ----------------------------------------------------
__device__ __forceinline__ float to_tf32(float x) {
    float r; asm("cvt.rna.tf32.f32 %0, %1;" : "=f"(r) : "f"(x)); return r;
}
__device__ __forceinline__ uint32_t smem_u32(const void* p) {
    uint32_t a;
    asm("{ .reg .u64 t; cvta.to.shared.u64 t, %1; cvt.u32.u64 %0, t; }"
        : "=r"(a) : "l"(p));
    return a;
}
__device__ __forceinline__ void cp16(uint32_t dst, const void* src) {
    asm volatile("cp.async.cg.shared.global [%0], [%1], 16;"
                 :: "r"(dst), "l"(src) : "memory");
}
__device__ __forceinline__ void cp_commit() {
    asm volatile("cp.async.commit_group;" ::: "memory");
}
// ldmatrix x4: four 8x8 b16 tiles (== four 8x4 f32 tiles, tf32 fragment layout)
__device__ __forceinline__ void ldsm4(uint32_t* r, uint32_t addr) {
    asm volatile("ldmatrix.sync.aligned.m8n8.x4.shared.b16 {%0,%1,%2,%3}, [%4];"
                 : "=r"(r[0]), "=r"(r[1]), "=r"(r[2]), "=r"(r[3]) : "r"(addr));
}
// m16n8k8 tf32: C += A*B
__device__ __forceinline__ void mma8(float* c, uint32_t a0, uint32_t a1,
                                     uint32_t a2, uint32_t a3,
                                     uint32_t b0, uint32_t b1) {
    asm volatile(
        "mma.sync.aligned.m16n8k8.row.col.f32.tf32.tf32.f32 "
        "{%0,%1,%2,%3}, {%4,%5,%6,%7}, {%8,%9}, {%0,%1,%2,%3};"
        : "+f"(c[0]), "+f"(c[1]), "+f"(c[2]), "+f"(c[3])
        : "r"(a0), "r"(a1), "r"(a2), "r"(a3), "r"(b0), "r"(b1));
}
// m16n8k16 bf16: C += A*B
__device__ __forceinline__ void mma16bf(float* c, const uint32_t* a,
                                        uint32_t b0, uint32_t b1) {
    asm volatile(
        "mma.sync.aligned.m16n8k16.row.col.f32.bf16.bf16.f32 "
        "{%0,%1,%2,%3}, {%4,%5,%6,%7}, {%8,%9}, {%0,%1,%2,%3};"
        : "+f"(c[0]), "+f"(c[1]), "+f"(c[2]), "+f"(c[3])
        : "r"(a[0]), "r"(a[1]), "r"(a[2]), "r"(a[3]), "r"(b0), "r"(b1));
}
__device__ __forceinline__ uint32_t bf16pk(float lo, float hi) {
    uint32_t r;
    asm("cvt.rn.bf16x2.f32 %0, %1, %2;" : "=r"(r) : "f"(hi), "f"(lo));
    return r;
}

// ---------------- fused tf32 rounding for ALL weights ------------------------
#define NDD4 (D_*D_/4)      // 262144 float4 per DxD weight
#define NDF4 (DFF_*D_/4)    // 1048576 float4 per DFFxD weight
#define CVT_TOTAL (4*NDD4 + 2*NDF4)

__global__ __launch_bounds__(256) void cvt_all_kernel(
    const float* __restrict__ Wq, const float* __restrict__ Wk,
    const float* __restrict__ Wv, const float* __restrict__ Wo,
    const float* __restrict__ W1, const float* __restrict__ W2,
    float* __restrict__ wqkv, float* __restrict__ wo,
    float* __restrict__ w1, float* __restrict__ w2)
{
    int i = blockIdx.x * 256 + threadIdx.x;
    const float4* src; float4* dst; int off;
    if (i < 3 * NDD4) {          // packed qkv
        if (i < NDD4)          { src = (const float4*)Wq; off = i; }
        else if (i < 2*NDD4)   { src = (const float4*)Wk; off = i - NDD4; }
        else                   { src = (const float4*)Wv; off = i - 2*NDD4; }
        dst = (float4*)wqkv + (i - off ? (i < 2*NDD4 ? NDD4 : 2*NDD4) : 0);
        dst = (float4*)wqkv + (i - off);   // segment base in dst
    } else if (i < 4 * NDD4) { src = (const float4*)Wo; off = i - 3*NDD4; dst = (float4*)wo; }
    else if (i < 4*NDD4 + NDF4) { src = (const float4*)W1; off = i - 4*NDD4; dst = (float4*)w1; }
    else { src = (const float4*)W2; off = i - 4*NDD4 - NDF4; dst = (float4*)w2; }
    if (i < 3 * NDD4) { dst = (float4*)wqkv; off = i; src = (i < NDD4) ? (const float4*)Wq
                         : (i < 2*NDD4) ? (const float4*)Wk : (const float4*)Wv;
                        // src index within its own matrix:
                        ; }
    // recompute cleanly to avoid the messy branches above:
    int si;
    if (i < NDD4)            { src = (const float4*)Wq; si = i;            dst = (float4*)wqkv; off = i; }
    else if (i < 2*NDD4)     { src = (const float4*)Wk; si = i - NDD4;     dst = (float4*)wqkv; off = i; }
    else if (i < 3*NDD4)     { src = (const float4*)Wv; si = i - 2*NDD4;   dst = (float4*)wqkv; off = i; }
    else if (i < 4*NDD4)     { src = (const float4*)Wo; si = i - 3*NDD4;   dst = (float4*)wo;   off = si; }
    else if (i < 4*NDD4+NDF4){ src = (const float4*)W1; si = i - 4*NDD4;   dst = (float4*)w1;   off = si; }
    else                     { src = (const float4*)W2; si = i - 4*NDD4 - NDF4; dst = (float4*)w2; off = si; }
    float4 v = src[si];
    v.x = to_tf32(v.x); v.y = to_tf32(v.y);
    v.z = to_tf32(v.z); v.w = to_tf32(v.w);
    dst[off] = v;
}

__global__ __launch_bounds__(256) void pack_bias_kernel(
    const float* __restrict__ a, const float* __restrict__ b,
    const float* __restrict__ c, float* __restrict__ o)
{
    int i = blockIdx.x * 256 + threadIdx.x;
    if (i < D_) { o[i] = a[i]; o[D_ + i] = b[i]; o[2*D_ + i] = c[i]; }
}

// ---------------- LayerNorm ---------------------------------------------------
template <int RND>
__global__ __launch_bounds__(256) void ln_kernel(
    const float* __restrict__ x, const float* __restrict__ g,
    const float* __restrict__ bta, float* __restrict__ out)
{
    const int row = blockIdx.x;
    const int t   = threadIdx.x;
    const float4* xr = (const float4*)(x + (size_t)row * D_);
    float4 v = xr[t];
    float s  = v.x + v.y + v.z + v.w;
    float s2 = v.x*v.x + v.y*v.y + v.z*v.z + v.w*v.w;
    #pragma unroll
    for (int o = 16; o > 0; o >>= 1) {
        s  += __shfl_xor_sync(0xffffffffu, s,  o);
        s2 += __shfl_xor_sync(0xffffffffu, s2, o);
    }
    __shared__ float rs[8], rs2[8];
    const int w = t >> 5;
    if ((t & 31) == 0) { rs[w] = s; rs2[w] = s2; }
    __syncthreads();
    s = 0.f; s2 = 0.f;
    #pragma unroll
    for (int i = 0; i < 8; i++) { s += rs[i]; s2 += rs2[i]; }
    const float mu   = s * (1.0f / D_);
    const float var  = s2 * (1.0f / D_) - mu * mu;
    const float rstd = rsqrtf(var + 1e-5f);
    float4 gg = ((const float4*)g)[t];
    float4 bb = ((const float4*)bta)[t];
    float4 o4;
    o4.x = (v.x - mu) * rstd * gg.x + bb.x;
    o4.y = (v.y - mu) * rstd * gg.y + bb.y;
    o4.z = (v.z - mu) * rstd * gg.z + bb.z;
    o4.w = (v.w - mu) * rstd * gg.w + bb.w;
    if (RND) {
        o4.x = to_tf32(o4.x); o4.y = to_tf32(o4.y);
        o4.z = to_tf32(o4.z); o4.w = to_tf32(o4.w);
    }
    ((float4*)(out + (size_t)row * D_))[t] = o4;
}

// ---------------- TF32 tensor-core GEMM-NT (3-stage cp.async pipeline) -------
enum { EPI_NONE = 0, EPI_RES = 1, EPI_GELU = 2 };
#define STAGES 3
#define STAGE_BYTES 32768
#define GEMM_SMEM (STAGES * STAGE_BYTES)   // 96 KB

template <int EPI>
__global__ __launch_bounds__(256, 2) void gemm_mma(
    int M, int N, int K,
    const float* __restrict__ A, const float* __restrict__ Bw,
    const float* __restrict__ bias, const float* __restrict__ resid,
    float* __restrict__ C)
{
    extern __shared__ float sm[];   // [3][8192]: per stage: A 4096 floats, B 4096
    const int tid  = threadIdx.x;
    const int lane = tid & 31;
    const int wid  = tid >> 5;
    const int wm = wid & 1;
    const int wn = wid >> 1;
    const int brow = blockIdx.y * 128;
    const int bcol = blockIdx.x * 128;
    const int T = K >> 5;

    const uint32_t smb = smem_u32(sm);

    int am[4], akq[4];
    #pragma unroll
    for (int p = 0; p < 4; p++) {
        const int c = tid + 256 * p;
        am[p]  = c >> 3;
        akq[p] = c & 7;
    }

    float acc[4][4][4];
    #pragma unroll
    for (int mi = 0; mi < 4; mi++)
        #pragma unroll
        for (int ni = 0; ni < 4; ni++)
            #pragma unroll
            for (int e = 0; e < 4; e++) acc[mi][ni][e] = 0.f;

    auto issue = [&](int i, int stg) {
        const uint32_t dA = smb + (uint32_t)stg * STAGE_BYTES;
        const uint32_t dB = dA + 16384u;
        const int kbase = i * 32;
        #pragma unroll
        for (int p = 0; p < 4; p++) {
            const int m = am[p], kq = akq[p];
            const uint32_t doff = (uint32_t)(m * 128 + (((kq ^ (m & 7)) << 4)));
            cp16(dA + doff, A  + (size_t)(brow + m) * K + kbase + kq * 4);
            cp16(dB + doff, Bw + (size_t)(bcol + m) * K + kbase + kq * 4);
        }
        cp_commit();
    };

    // ldmatrix lane addressing (f32 index = row*32 + (k ^ ((row&7)<<2)))
    const int a_mb  = (lane & 7) + (((lane >> 3) & 1) << 3);
    const int a_kf  = (lane >> 4) << 2;
    const int b_nb  = (lane & 7) + ((lane >> 4) << 3);
    const int b_kf  = ((lane >> 3) & 1) << 2;
    const int xsh   = (lane & 7) << 2;
    uint32_t amrow[4], bnrow[2];
    #pragma unroll
    for (int mi = 0; mi < 4; mi++)
        amrow[mi] = (uint32_t)((wm * 64 + mi * 16 + a_mb) * 32);
    #pragma unroll
    for (int g = 0; g < 2; g++)
        bnrow[g] = (uint32_t)(4096 + (wn * 32 + g * 16 + b_nb) * 32);

    issue(0, 0);
    issue(1, 1);

    int stg = 0;
    for (int i = 0; i < T; i++) {
        if (i < T - 1) asm volatile("cp.async.wait_group 1;" ::: "memory");
        else           asm volatile("cp.async.wait_group 0;" ::: "memory");
        __syncthreads();

        // prefetch k-tile i+2 into the stage freed at iteration i-1
        if (i + 2 < T) {
            int nstg = stg + 2; if (nstg >= STAGES) nstg -= STAGES;
            issue(i + 2, nstg);
        }

        const uint32_t bufb = smb + (uint32_t)stg * STAGE_BYTES;

        #pragma unroll
        for (int s = 0; s < 4; s++) {
            const int k0 = s * 8;
            const uint32_t kA = (uint32_t)((k0 + a_kf) ^ xsh);
            const uint32_t kB = (uint32_t)((k0 + b_kf) ^ xsh);
            uint32_t af[4][4], bfr[2][4];
            #pragma unroll
            for (int mi = 0; mi < 4; mi++)
                ldsm4(af[mi], bufb + 4u * (amrow[mi] + kA));
            #pragma unroll
            for (int g = 0; g < 2; g++)
                ldsm4(bfr[g], bufb + 4u * (bnrow[g] + kB));
            #pragma unroll
            for (int mi = 0; mi < 4; mi++)
                #pragma unroll
                for (int ni = 0; ni < 4; ni++)
                    mma8(acc[mi][ni], af[mi][0], af[mi][1], af[mi][2], af[mi][3],
                         bfr[ni >> 1][(ni & 1) * 2], bfr[ni >> 1][(ni & 1) * 2 + 1]);
        }
        if (++stg == STAGES) stg = 0;
    }

    #pragma unroll
    for (int mi = 0; mi < 4; mi++) {
        #pragma unroll
        for (int ni = 0; ni < 4; ni++) {
            const int r0  = brow + wm * 64 + mi * 16 + (lane >> 2);
            const int col = bcol + wn * 32 + ni * 8 + 2 * (lane & 3);
            const float b0 = bias[col], b1 = bias[col + 1];
            float v[4] = { acc[mi][ni][0] + b0, acc[mi][ni][1] + b1,
                           acc[mi][ni][2] + b0, acc[mi][ni][3] + b1 };
            if (EPI == EPI_RES) {
                const float2 x0 = *(const float2*)&resid[(size_t)r0 * N + col];
                const float2 x1 = *(const float2*)&resid[(size_t)(r0 + 8) * N + col];
                v[0] += x0.x; v[1] += x0.y; v[2] += x1.x; v[3] += x1.y;
            }
            if (EPI == EPI_GELU) {
                #pragma unroll
                for (int e = 0; e < 4; e++) {
                    v[e] = 0.5f * v[e] * (1.0f + erff(v[e] * 0.70710678118654752f));
                    v[e] = to_tf32(v[e]);
                }
            }
            *(float2*)&C[(size_t)r0 * N + col]       = make_float2(v[0], v[1]);
            *(float2*)&C[(size_t)(r0 + 8) * N + col] = make_float2(v[2], v[3]);
        }
    }
}

// ---------------- tensor-core flash attention --------------------------------
__global__ __launch_bounds__(256) void attn_mma(
    const float* __restrict__ QKV, const int* __restrict__ mask,
    float* __restrict__ O)
{
    __shared__ __align__(16) float Ks[64][68];          // [key][dk] fp32
    __shared__ __align__(16) __nv_bfloat16 Vs[64][72];  // [dk][key] bf16

    const int b = blockIdx.z, h = blockIdx.y;
    const int tid = threadIdx.x, lane = tid & 31, wid = tid >> 5;
    const int gp = lane >> 2, tg = lane & 3;
    const int qrow0 = blockIdx.x * 128 + wid * 16 + gp;

    const float* Qb = QKV + (size_t)(b * S_) * QKV_S + h * DK_;
    const float* Kb = Qb + D_;
    const float* Vb = Qb + 2 * D_;

    uint32_t qf[8][4];
    {
        const float* q0p = Qb + (size_t)qrow0 * QKV_S;
        const float* q1p = q0p + (size_t)8 * QKV_S;
        #pragma unroll
        for (int s = 0; s < 8; s++) {
            qf[s][0] = __float_as_uint(q0p[tg + 8*s]     * 0.125f);
            qf[s][1] = __float_as_uint(q1p[tg + 8*s]     * 0.125f);
            qf[s][2] = __float_as_uint(q0p[tg + 8*s + 4] * 0.125f);
            qf[s][3] = __float_as_uint(q1p[tg + 8*s + 4] * 0.125f);
        }
    }

    float oa[8][4];
    #pragma unroll
    for (int j = 0; j < 8; j++)
        #pragma unroll
        for (int e = 0; e < 4; e++) oa[j][e] = 0.f;
    float m0c = -1e30f, m1c = -1e30f, l0 = 0.f, l1 = 0.f;

    const int* mr0 = mask + ((size_t)(b * S_ + qrow0)) * S_;
    const int* mr1 = mr0 + (size_t)8 * S_;

    for (int kt = 0; kt < S_; kt += 64) {
        #pragma unroll
        for (int p = 0; p < 4; p++) {
            const int c = tid + 256 * p;
            const int key = c >> 4, d4 = (c & 15) * 4;
            const size_t gk = (size_t)(kt + key) * QKV_S + d4;
            float4 k4 = *(const float4*)&Kb[gk];
            *(float4*)&Ks[key][d4] = k4;
            float4 v4 = *(const float4*)&Vb[gk];
            Vs[d4 + 0][key] = __float2bfloat16(v4.x);
            Vs[d4 + 1][key] = __float2bfloat16(v4.y);
            Vs[d4 + 2][key] = __float2bfloat16(v4.z);
            Vs[d4 + 3][key] = __float2bfloat16(v4.w);
        }
        __syncthreads();

        float sc[8][4];
        #pragma unroll
        for (int j = 0; j < 8; j++)
            #pragma unroll
            for (int e = 0; e < 4; e++) sc[j][e] = 0.f;
        #pragma unroll
        for (int s = 0; s < 8; s++) {
            #pragma unroll
            for (int j = 0; j < 8; j++) {
                const uint32_t kb0 = __float_as_uint(Ks[8*j + gp][tg + 8*s]);
                const uint32_t kb1 = __float_as_uint(Ks[8*j + gp][tg + 8*s + 4]);
                mma8(sc[j], qf[s][0], qf[s][1], qf[s][2], qf[s][3], kb0, kb1);
            }
        }

        #pragma unroll
        for (int j = 0; j < 8; j++) {
            const int2 mm0 = *(const int2*)&mr0[kt + 8*j + 2*tg];
            const int2 mm1 = *(const int2*)&mr1[kt + 8*j + 2*tg];
            if (mm0.x) sc[j][0] = -10000.0f;
            if (mm0.y) sc[j][1] = -10000.0f;
            if (mm1.x) sc[j][2] = -10000.0f;
            if (mm1.y) sc[j][3] = -10000.0f;
        }

        float t0 = -1e30f, t1 = -1e30f;
        #pragma unroll
        for (int j = 0; j < 8; j++) {
            t0 = fmaxf(t0, fmaxf(sc[j][0], sc[j][1]));
            t1 = fmaxf(t1, fmaxf(sc[j][2], sc[j][3]));
        }
        t0 = fmaxf(t0, __shfl_xor_sync(0xffffffffu, t0, 1));
        t0 = fmaxf(t0, __shfl_xor_sync(0xffffffffu, t0, 2));
        t1 = fmaxf(t1, __shfl_xor_sync(0xffffffffu, t1, 1));
        t1 = fmaxf(t1, __shfl_xor_sync(0xffffffffu, t1, 2));
        const float mn0 = fmaxf(m0c, t0), mn1 = fmaxf(m1c, t1);
        const float cr0 = __expf(m0c - mn0), cr1 = __expf(m1c - mn1);
        float ps0 = 0.f, ps1 = 0.f;
        #pragma unroll
        for (int j = 0; j < 8; j++) {
            sc[j][0] = __expf(sc[j][0] - mn0); ps0 += sc[j][0];
            sc[j][1] = __expf(sc[j][1] - mn0); ps0 += sc[j][1];
            sc[j][2] = __expf(sc[j][2] - mn1); ps1 += sc[j][2];
            sc[j][3] = __expf(sc[j][3] - mn1); ps1 += sc[j][3];
        }
        ps0 += __shfl_xor_sync(0xffffffffu, ps0, 1);
        ps0 += __shfl_xor_sync(0xffffffffu, ps0, 2);
        ps1 += __shfl_xor_sync(0xffffffffu, ps1, 1);
        ps1 += __shfl_xor_sync(0xffffffffu, ps1, 2);
        l0 = l0 * cr0 + ps0; m0c = mn0;
        l1 = l1 * cr1 + ps1; m1c = mn1;
        #pragma unroll
        for (int j = 0; j < 8; j++) {
            oa[j][0] *= cr0; oa[j][1] *= cr0;
            oa[j][2] *= cr1; oa[j][3] *= cr1;
        }

        uint32_t pa[4][4];
        #pragma unroll
        for (int t = 0; t < 4; t++) {
            pa[t][0] = bf16pk(sc[2*t][0],     sc[2*t][1]);
            pa[t][1] = bf16pk(sc[2*t][2],     sc[2*t][3]);
            pa[t][2] = bf16pk(sc[2*t + 1][0], sc[2*t + 1][1]);
            pa[t][3] = bf16pk(sc[2*t + 1][2], sc[2*t + 1][3]);
        }

        #pragma unroll
        for (int j = 0; j < 8; j++) {
            #pragma unroll
            for (int t = 0; t < 4; t++) {
                const uint32_t vb0 =
                    *(const uint32_t*)&Vs[8*j + gp][16*t + 2*tg];
                const uint32_t vb1 =
                    *(const uint32_t*)&Vs[8*j + gp][16*t + 8 + 2*tg];
                mma16bf(oa[j], pa[t], vb0, vb1);
            }
        }
        __syncthreads();
    }

    const float inv0 = 1.0f / l0, inv1 = 1.0f / l1;
    float* o0 = O + ((size_t)(b * S_ + qrow0)) * D_ + h * DK_;
    float* o1 = o0 + (size_t)8 * D_;
    #pragma unroll
    for (int j = 0; j < 8; j++) {
        *(float2*)&o0[8*j + 2*tg] =
            make_float2(to_tf32(oa[j][0] * inv0), to_tf32(oa[j][1] * inv0));
        *(float2*)&o1[8*j + 2*tg] =
            make_float2(to_tf32(oa[j][2] * inv1), to_tf32(oa[j][3] * inv1));
    }
}

// ---------------- launcher ----------------------------------------------------
extern "C" void kernel_launch(void* const* d_in, const int* in_sizes, int n_in,
                              void* d_out, int out_size)
{
    const float* x  = (const float*)d_in[0];
    const int*   mask = (const int*)d_in[1];
    const float* Wq = (const float*)d_in[2];  const float* bq = (const float*)d_in[3];
    const float* Wk = (const float*)d_in[4];  const float* bk = (const float*)d_in[5];
    const float* Wv = (const float*)d_in[6];  const float* bv = (const float*)d_in[7];
    const float* Wo = (const float*)d_in[8];  const float* bo = (const float*)d_in[9];
    const float* W1 = (const float*)d_in[10]; const float* b1 = (const float*)d_in[11];
    const float* W2 = (const float*)d_in[12]; const float* b2 = (const float*)d_in[13];
    const float* ga = (const float*)d_in[14]; const float* ba = (const float*)d_in[15];
    const float* gf = (const float*)d_in[16]; const float* bf = (const float*)d_in[17];
    float* out = (float*)d_out;

    float *nx, *x1, *qkv, *hb, *wqkv, *bqkv, *wo, *w1, *w2;
    cudaGetSymbolAddress((void**)&nx,   g_bufA);
    cudaGetSymbolAddress((void**)&x1,   g_x1);
    cudaGetSymbolAddress((void**)&qkv,  g_qkv);
    cudaGetSymbolAddress((void**)&hb,   g_h);
    cudaGetSymbolAddress((void**)&wqkv, g_wqkv);
    cudaGetSymbolAddress((void**)&bqkv, g_bqkv);
    cudaGetSymbolAddress((void**)&wo,   g_wo);
    cudaGetSymbolAddress((void**)&w1,   g_w1);
    cudaGetSymbolAddress((void**)&w2,   g_w2);

    cudaFuncSetAttribute(gemm_mma<EPI_NONE>,
                         cudaFuncAttributeMaxDynamicSharedMemorySize, GEMM_SMEM);
    cudaFuncSetAttribute(gemm_mma<EPI_RES>,
                         cudaFuncAttributeMaxDynamicSharedMemorySize, GEMM_SMEM);
    cudaFuncSetAttribute(gemm_mma<EPI_GELU>,
                         cudaFuncAttributeMaxDynamicSharedMemorySize, GEMM_SMEM);

    // 0: all weight cvt in ONE kernel; 1: bias pack; 2: LN; 3: QKV GEMM (ncu slot)
    cvt_all_kernel<<<CVT_TOTAL / 256, 256>>>(Wq, Wk, Wv, Wo, W1, W2,
                                             wqkv, wo, w1, w2);
    pack_bias_kernel<<<(D_ + 255) / 256, 256>>>(bq, bk, bv, bqkv);
    ln_kernel<1><<<ROWS, 256>>>(x, ga, ba, nx);

    dim3 gqkv(QKV_S / 128, ROWS / 128);
    gemm_mma<EPI_NONE><<<gqkv, 256, GEMM_SMEM>>>(ROWS, QKV_S, D_, nx, wqkv, bqkv,
                                                 nullptr, qkv);

    attn_mma<<<dim3(S_ / 128, H_, B_), 256>>>(qkv, mask, nx);

    dim3 g1(D_ / 128, ROWS / 128);
    gemm_mma<EPI_RES><<<g1, 256, GEMM_SMEM>>>(ROWS, D_, D_, nx, wo, bo, x, x1);

    ln_kernel<1><<<ROWS, 256>>>(x1, gf, bf, qkv);

    dim3 g2(DFF_ / 128, ROWS / 128);
    gemm_mma<EPI_GELU><<<g2, 256, GEMM_SMEM>>>(ROWS, DFF_, D_, qkv, w1, b1,
                                               nullptr, hb);

    gemm_mma<EPI_RES><<<g1, 256, GEMM_SMEM>>>(ROWS, D_, DFF_, hb, w2, b2, x1, out);
}

// round 8
// speedup vs baseline: 1.0271x; 1.0271x over previous
#include <cuda_runtime.h>
#include <cuda_bf16.h>
#include <cstdint>

#define B_   2
#define S_   2048
#define D_   1024
#define H_   16
#define DK_  64
#define DFF_ 4096
#define ROWS (B_*S_)     // 4096
#define QKV_S (3*D_)     // 3072

// ---------------- scratch (device globals; no allocations allowed) ----------
__device__ float g_bufA[ROWS*D_];      // nx -> ctx
__device__ float g_x1 [ROWS*D_];       // x after attn residual
__device__ float g_qkv[ROWS*QKV_S];    // packed q|k|v ; later reused as nx2
__device__ float g_h  [ROWS*DFF_];     // ffn hidden
// tf32-rounded weights
__device__ float g_wqkv[3*D_*D_];
__device__ float g_bqkv[3*D_];
__device__ float g_wo[D_*D_];
__device__ float g_w1[DFF_*D_], g_w2[D_*DFF_];

// ---------------- helpers ----------------------------------------------------
__device__ __forceinline__ float to_tf32(float x) {
    float r; asm("cvt.rna.tf32.f32 %0, %1;" : "=f"(r) : "f"(x)); return r;
}
__device__ __forceinline__ uint32_t smem_u32(const void* p) {
    uint32_t a;
    asm("{ .reg .u64 t; cvta.to.shared.u64 t, %1; cvt.u32.u64 %0, t; }"
        : "=r"(a) : "l"(p));
    return a;
}
__device__ __forceinline__ void cp16(uint32_t dst, const void* src) {
    asm volatile("cp.async.cg.shared.global [%0], [%1], 16;"
                 :: "r"(dst), "l"(src) : "memory");
}
__device__ __forceinline__ void cp_commit() {
    asm volatile("cp.async.commit_group;" ::: "memory");
}
// ldmatrix x4: four 8x8 b16 tiles (== four 8x4 f32 tiles, tf32 fragment layout)
__device__ __forceinline__ void ldsm4(uint32_t* r, uint32_t addr) {
    asm volatile("ldmatrix.sync.aligned.m8n8.x4.shared.b16 {%0,%1,%2,%3}, [%4];"
                 : "=r"(r[0]), "=r"(r[1]), "=r"(r[2]), "=r"(r[3]) : "r"(addr));
}
// m16n8k8 tf32: C += A*B
__device__ __forceinline__ void mma8(float* c, uint32_t a0, uint32_t a1,
                                     uint32_t a2, uint32_t a3,
                                     uint32_t b0, uint32_t b1) {
    asm volatile(
        "mma.sync.aligned.m16n8k8.row.col.f32.tf32.tf32.f32 "
        "{%0,%1,%2,%3}, {%4,%5,%6,%7}, {%8,%9}, {%0,%1,%2,%3};"
        : "+f"(c[0]), "+f"(c[1]), "+f"(c[2]), "+f"(c[3])
        : "r"(a0), "r"(a1), "r"(a2), "r"(a3), "r"(b0), "r"(b1));
}
// m16n8k16 bf16: C += A*B
__device__ __forceinline__ void mma16bf(float* c, const uint32_t* a,
                                        uint32_t b0, uint32_t b1) {
    asm volatile(
        "mma.sync.aligned.m16n8k16.row.col.f32.bf16.bf16.f32 "
        "{%0,%1,%2,%3}, {%4,%5,%6,%7}, {%8,%9}, {%0,%1,%2,%3};"
        : "+f"(c[0]), "+f"(c[1]), "+f"(c[2]), "+f"(c[3])
        : "r"(a[0]), "r"(a[1]), "r"(a[2]), "r"(a[3]), "r"(b0), "r"(b1));
}
__device__ __forceinline__ uint32_t bf16pk(float lo, float hi) {
    uint32_t r;
    asm("cvt.rn.bf16x2.f32 %0, %1, %2;" : "=r"(r) : "f"(hi), "f"(lo));
    return r;
}

// ---------------- fused tf32 rounding for ALL weights ------------------------
#define NDD4 (D_*D_/4)      // float4 count per DxD weight
#define NDF4 (DFF_*D_/4)    // float4 count per DFFxD weight
#define CVT_TOTAL (4*NDD4 + 2*NDF4)

__global__ __launch_bounds__(256) void cvt_all_kernel(
    const float* __restrict__ Wq, const float* __restrict__ Wk,
    const float* __restrict__ Wv, const float* __restrict__ Wo,
    const float* __restrict__ W1, const float* __restrict__ W2,
    float* __restrict__ wqkv, float* __restrict__ wo,
    float* __restrict__ w1, float* __restrict__ w2)
{
    const int i = blockIdx.x * 256 + threadIdx.x;
    const float4* src; float4* dst; int si, off;
    if (i < NDD4)             { src = (const float4*)Wq; si = i;                dst = (float4*)wqkv; off = i; }
    else if (i < 2*NDD4)      { src = (const float4*)Wk; si = i - NDD4;         dst = (float4*)wqkv; off = i; }
    else if (i < 3*NDD4)      { src = (const float4*)Wv; si = i - 2*NDD4;       dst = (float4*)wqkv; off = i; }
    else if (i < 4*NDD4)      { src = (const float4*)Wo; si = i - 3*NDD4;       dst = (float4*)wo;   off = si; }
    else if (i < 4*NDD4+NDF4) { src = (const float4*)W1; si = i - 4*NDD4;       dst = (float4*)w1;   off = si; }
    else                      { src = (const float4*)W2; si = i - 4*NDD4-NDF4;  dst = (float4*)w2;   off = si; }
    float4 v = src[si];
    v.x = to_tf32(v.x); v.y = to_tf32(v.y);
    v.z = to_tf32(v.z); v.w = to_tf32(v.w);
    dst[off] = v;
}

__global__ __launch_bounds__(256) void pack_bias_kernel(
    const float* __restrict__ a, const float* __restrict__ b,
    const float* __restrict__ c, float* __restrict__ o)
{
    int i = blockIdx.x * 256 + threadIdx.x;
    if (i < D_) { o[i] = a[i]; o[D_ + i] = b[i]; o[2*D_ + i] = c[i]; }
}

// ---------------- LayerNorm ---------------------------------------------------
template <int RND>
__global__ __launch_bounds__(256) void ln_kernel(
    const float* __restrict__ x, const float* __restrict__ g,
    const float* __restrict__ bta, float* __restrict__ out)
{
    const int row = blockIdx.x;
    const int t   = threadIdx.x;
    const float4* xr = (const float4*)(x + (size_t)row * D_);
    float4 v = xr[t];
    float s  = v.x + v.y + v.z + v.w;
    float s2 = v.x*v.x + v.y*v.y + v.z*v.z + v.w*v.w;
    #pragma unroll
    for (int o = 16; o > 0; o >>= 1) {
        s  += __shfl_xor_sync(0xffffffffu, s,  o);
        s2 += __shfl_xor_sync(0xffffffffu, s2, o);
    }
    __shared__ float rs[8], rs2[8];
    const int w = t >> 5;
    if ((t & 31) == 0) { rs[w] = s; rs2[w] = s2; }
    __syncthreads();
    s = 0.f; s2 = 0.f;
    #pragma unroll
    for (int i = 0; i < 8; i++) { s += rs[i]; s2 += rs2[i]; }
    const float mu   = s * (1.0f / D_);
    const float var  = s2 * (1.0f / D_) - mu * mu;
    const float rstd = rsqrtf(var + 1e-5f);
    float4 gg = ((const float4*)g)[t];
    float4 bb = ((const float4*)bta)[t];
    float4 o4;
    o4.x = (v.x - mu) * rstd * gg.x + bb.x;
    o4.y = (v.y - mu) * rstd * gg.y + bb.y;
    o4.z = (v.z - mu) * rstd * gg.z + bb.z;
    o4.w = (v.w - mu) * rstd * gg.w + bb.w;
    if (RND) {
        o4.x = to_tf32(o4.x); o4.y = to_tf32(o4.y);
        o4.z = to_tf32(o4.z); o4.w = to_tf32(o4.w);
    }
    ((float4*)(out + (size_t)row * D_))[t] = o4;
}

// ---------------- TF32 GEMM-NT: 4 warps, warp tile 64x64 ---------------------
enum { EPI_NONE = 0, EPI_RES = 1, EPI_GELU = 2 };
#define STAGES 3
#define STAGE_BYTES 32768
#define GEMM_SMEM (STAGES * STAGE_BYTES)   // 96 KB

template <int EPI>
__global__ __launch_bounds__(128, 2) void gemm_mma(
    int M, int N, int K,
    const float* __restrict__ A, const float* __restrict__ Bw,
    const float* __restrict__ bias, const float* __restrict__ resid,
    float* __restrict__ C)
{
    extern __shared__ float sm[];   // [3][8192]: per stage: A 4096 floats, B 4096
    const int tid  = threadIdx.x;
    const int lane = tid & 31;
    const int wid  = tid >> 5;      // 0..3
    const int wm = wid & 1;         // 64-row slice
    const int wn = wid >> 1;        // 64-col slice
    const int brow = blockIdx.y * 128;
    const int bcol = blockIdx.x * 128;
    const int T = K >> 5;

    const uint32_t smb = smem_u32(sm);

    // cp.async mapping: 128 threads x 8 chunks cover 1024 float4 per matrix
    int am[8], akq[8];
    #pragma unroll
    for (int p = 0; p < 8; p++) {
        const int c = tid + 128 * p;   // 0..1023
        am[p]  = c >> 3;               // row 0..127
        akq[p] = c & 7;                // 16B chunk in row
    }

    float acc[4][8][4];
    #pragma unroll
    for (int mi = 0; mi < 4; mi++)
        #pragma unroll
        for (int ni = 0; ni < 8; ni++)
            #pragma unroll
            for (int e = 0; e < 4; e++) acc[mi][ni][e] = 0.f;

    auto issue = [&](int i, int stg) {
        const uint32_t dA = smb + (uint32_t)stg * STAGE_BYTES;
        const uint32_t dB = dA + 16384u;
        const int kbase = i * 32;
        #pragma unroll
        for (int p = 0; p < 8; p++) {
            const int m = am[p], kq = akq[p];
            const uint32_t doff = (uint32_t)(m * 128 + (((kq ^ (m & 7)) << 4)));
            cp16(dA + doff, A  + (size_t)(brow + m) * K + kbase + kq * 4);
            cp16(dB + doff, Bw + (size_t)(bcol + m) * K + kbase + kq * 4);
        }
        cp_commit();
    };

    // ldmatrix lane addressing (f32 index = row*32 + (k ^ ((row&7)<<2)))
    const int a_mb  = (lane & 7) + (((lane >> 3) & 1) << 3);
    const int a_kf  = (lane >> 4) << 2;
    const int b_nb  = (lane & 7) + ((lane >> 4) << 3);
    const int b_kf  = ((lane >> 3) & 1) << 2;
    const int xsh   = (lane & 7) << 2;
    uint32_t amrow[4], bnrow[4];
    #pragma unroll
    for (int mi = 0; mi < 4; mi++)
        amrow[mi] = (uint32_t)((wm * 64 + mi * 16 + a_mb) * 32);
    #pragma unroll
    for (int g = 0; g < 4; g++)
        bnrow[g] = (uint32_t)(4096 + (wn * 64 + g * 16 + b_nb) * 32);

    issue(0, 0);
    issue(1, 1);

    int stg = 0;
    for (int i = 0; i < T; i++) {
        if (i < T - 1) asm volatile("cp.async.wait_group 1;" ::: "memory");
        else           asm volatile("cp.async.wait_group 0;" ::: "memory");
        __syncthreads();

        if (i + 2 < T) {
            int nstg = stg + 2; if (nstg >= STAGES) nstg -= STAGES;
            issue(i + 2, nstg);
        }

        const uint32_t bufb = smb + (uint32_t)stg * STAGE_BYTES;

        #pragma unroll
        for (int s = 0; s < 4; s++) {
            const int k0 = s * 8;
            const uint32_t kA = (uint32_t)((k0 + a_kf) ^ xsh);
            const uint32_t kB = (uint32_t)((k0 + b_kf) ^ xsh);
            uint32_t af[4][4], bfr[4][4];
            #pragma unroll
            for (int mi = 0; mi < 4; mi++)
                ldsm4(af[mi], bufb + 4u * (amrow[mi] + kA));
            #pragma unroll
            for (int g = 0; g < 4; g++)
                ldsm4(bfr[g], bufb + 4u * (bnrow[g] + kB));
            #pragma unroll
            for (int mi = 0; mi < 4; mi++)
                #pragma unroll
                for (int ni = 0; ni < 8; ni++)
                    mma8(acc[mi][ni], af[mi][0], af[mi][1], af[mi][2], af[mi][3],
                         bfr[ni >> 1][(ni & 1) * 2], bfr[ni >> 1][(ni & 1) * 2 + 1]);
        }
        if (++stg == STAGES) stg = 0;
    }

    #pragma unroll
    for (int mi = 0; mi < 4; mi++) {
        #pragma unroll
        for (int ni = 0; ni < 8; ni++) {
            const int r0  = brow + wm * 64 + mi * 16 + (lane >> 2);
            const int col = bcol + wn * 64 + ni * 8 + 2 * (lane & 3);
            const float b0 = bias[col], b1 = bias[col + 1];
            float v[4] = { acc[mi][ni][0] + b0, acc[mi][ni][1] + b1,
                           acc[mi][ni][2] + b0, acc[mi][ni][3] + b1 };
            if (EPI == EPI_RES) {
                const float2 x0 = *(const float2*)&resid[(size_t)r0 * N + col];
                const float2 x1 = *(const float2*)&resid[(size_t)(r0 + 8) * N + col];
                v[0] += x0.x; v[1] += x0.y; v[2] += x1.x; v[3] += x1.y;
            }
            if (EPI == EPI_GELU) {
                #pragma unroll
                for (int e = 0; e < 4; e++) {
                    v[e] = 0.5f * v[e] * (1.0f + erff(v[e] * 0.70710678118654752f));
                    v[e] = to_tf32(v[e]);
                }
            }
            *(float2*)&C[(size_t)r0 * N + col]       = make_float2(v[0], v[1]);
            *(float2*)&C[(size_t)(r0 + 8) * N + col] = make_float2(v[2], v[3]);
        }
    }
}

// ---------------- tensor-core flash attention --------------------------------
__global__ __launch_bounds__(256) void attn_mma(
    const float* __restrict__ QKV, const int* __restrict__ mask,
    float* __restrict__ O)
{
    __shared__ __align__(16) float Ks[64][68];          // [key][dk] fp32
    __shared__ __align__(16) __nv_bfloat16 Vs[64][72];  // [dk][key] bf16

    const int b = blockIdx.z, h = blockIdx.y;
    const int tid = threadIdx.x, lane = tid & 31, wid = tid >> 5;
    const int gp = lane >> 2, tg = lane & 3;
    const int qrow0 = blockIdx.x * 128 + wid * 16 + gp;

    const float* Qb = QKV + (size_t)(b * S_) * QKV_S + h * DK_;
    const float* Kb = Qb + D_;
    const float* Vb = Qb + 2 * D_;

    uint32_t qf[8][4];
    {
        const float* q0p = Qb + (size_t)qrow0 * QKV_S;
        const float* q1p = q0p + (size_t)8 * QKV_S;
        #pragma unroll
        for (int s = 0; s < 8; s++) {
            qf[s][0] = __float_as_uint(q0p[tg + 8*s]     * 0.125f);
            qf[s][1] = __float_as_uint(q1p[tg + 8*s]     * 0.125f);
            qf[s][2] = __float_as_uint(q0p[tg + 8*s + 4] * 0.125f);
            qf[s][3] = __float_as_uint(q1p[tg + 8*s + 4] * 0.125f);
        }
    }

    float oa[8][4];
    #pragma unroll
    for (int j = 0; j < 8; j++)
        #pragma unroll
        for (int e = 0; e < 4; e++) oa[j][e] = 0.f;
    float m0c = -1e30f, m1c = -1e30f, l0 = 0.f, l1 = 0.f;

    const int* mr0 = mask + ((size_t)(b * S_ + qrow0)) * S_;
    const int* mr1 = mr0 + (size_t)8 * S_;

    for (int kt = 0; kt < S_; kt += 64) {
        #pragma unroll
        for (int p = 0; p < 4; p++) {
            const int c = tid + 256 * p;
            const int key = c >> 4, d4 = (c & 15) * 4;
            const size_t gk = (size_t)(kt + key) * QKV_S + d4;
            float4 k4 = *(const float4*)&Kb[gk];
            *(float4*)&Ks[key][d4] = k4;
            float4 v4 = *(const float4*)&Vb[gk];
            Vs[d4 + 0][key] = __float2bfloat16(v4.x);
            Vs[d4 + 1][key] = __float2bfloat16(v4.y);
            Vs[d4 + 2][key] = __float2bfloat16(v4.z);
            Vs[d4 + 3][key] = __float2bfloat16(v4.w);
        }
        __syncthreads();

        float sc[8][4];
        #pragma unroll
        for (int j = 0; j < 8; j++)
            #pragma unroll
            for (int e = 0; e < 4; e++) sc[j][e] = 0.f;
        #pragma unroll
        for (int s = 0; s < 8; s++) {
            #pragma unroll
            for (int j = 0; j < 8; j++) {
                const uint32_t kb0 = __float_as_uint(Ks[8*j + gp][tg + 8*s]);
                const uint32_t kb1 = __float_as_uint(Ks[8*j + gp][tg + 8*s + 4]);
                mma8(sc[j], qf[s][0], qf[s][1], qf[s][2], qf[s][3], kb0, kb1);
            }
        }

        #pragma unroll
        for (int j = 0; j < 8; j++) {
            const int2 mm0 = *(const int2*)&mr0[kt + 8*j + 2*tg];
            const int2 mm1 = *(const int2*)&mr1[kt + 8*j + 2*tg];
            if (mm0.x) sc[j][0] = -10000.0f;
            if (mm0.y) sc[j][1] = -10000.0f;
            if (mm1.x) sc[j][2] = -10000.0f;
            if (mm1.y) sc[j][3] = -10000.0f;
        }

        float t0 = -1e30f, t1 = -1e30f;
        #pragma unroll
        for (int j = 0; j < 8; j++) {
            t0 = fmaxf(t0, fmaxf(sc[j][0], sc[j][1]));
            t1 = fmaxf(t1, fmaxf(sc[j][2], sc[j][3]));
        }
        t0 = fmaxf(t0, __shfl_xor_sync(0xffffffffu, t0, 1));
        t0 = fmaxf(t0, __shfl_xor_sync(0xffffffffu, t0, 2));
        t1 = fmaxf(t1, __shfl_xor_sync(0xffffffffu, t1, 1));
        t1 = fmaxf(t1, __shfl_xor_sync(0xffffffffu, t1, 2));
        const float mn0 = fmaxf(m0c, t0), mn1 = fmaxf(m1c, t1);
        const float cr0 = __expf(m0c - mn0), cr1 = __expf(m1c - mn1);
        float ps0 = 0.f, ps1 = 0.f;
        #pragma unroll
        for (int j = 0; j < 8; j++) {
            sc[j][0] = __expf(sc[j][0] - mn0); ps0 += sc[j][0];
            sc[j][1] = __expf(sc[j][1] - mn0); ps0 += sc[j][1];
            sc[j][2] = __expf(sc[j][2] - mn1); ps1 += sc[j][2];
            sc[j][3] = __expf(sc[j][3] - mn1); ps1 += sc[j][3];
        }
        ps0 += __shfl_xor_sync(0xffffffffu, ps0, 1);
        ps0 += __shfl_xor_sync(0xffffffffu, ps0, 2);
        ps1 += __shfl_xor_sync(0xffffffffu, ps1, 1);
        ps1 += __shfl_xor_sync(0xffffffffu, ps1, 2);
        l0 = l0 * cr0 + ps0; m0c = mn0;
        l1 = l1 * cr1 + ps1; m1c = mn1;
        #pragma unroll
        for (int j = 0; j < 8; j++) {
            oa[j][0] *= cr0; oa[j][1] *= cr0;
            oa[j][2] *= cr1; oa[j][3] *= cr1;
        }

        uint32_t pa[4][4];
        #pragma unroll
        for (int t = 0; t < 4; t++) {
            pa[t][0] = bf16pk(sc[2*t][0],     sc[2*t][1]);
            pa[t][1] = bf16pk(sc[2*t][2],     sc[2*t][3]);
            pa[t][2] = bf16pk(sc[2*t + 1][0], sc[2*t + 1][1]);
            pa[t][3] = bf16pk(sc[2*t + 1][2], sc[2*t + 1][3]);
        }

        #pragma unroll
        for (int j = 0; j < 8; j++) {
            #pragma unroll
            for (int t = 0; t < 4; t++) {
                const uint32_t vb0 =
                    *(const uint32_t*)&Vs[8*j + gp][16*t + 2*tg];
                const uint32_t vb1 =
                    *(const uint32_t*)&Vs[8*j + gp][16*t + 8 + 2*tg];
                mma16bf(oa[j], pa[t], vb0, vb1);
            }
        }
        __syncthreads();
    }

    const float inv0 = 1.0f / l0, inv1 = 1.0f / l1;
    float* o0 = O + ((size_t)(b * S_ + qrow0)) * D_ + h * DK_;
    float* o1 = o0 + (size_t)8 * D_;
    #pragma unroll
    for (int j = 0; j < 8; j++) {
        *(float2*)&o0[8*j + 2*tg] =
            make_float2(to_tf32(oa[j][0] * inv0), to_tf32(oa[j][1] * inv0));
        *(float2*)&o1[8*j + 2*tg] =
            make_float2(to_tf32(oa[j][2] * inv1), to_tf32(oa[j][3] * inv1));
    }
}

// ---------------- launcher ----------------------------------------------------
extern "C" void kernel_launch(void* const* d_in, const int* in_sizes, int n_in,
                              void* d_out, int out_size)
{
    const float* x  = (const float*)d_in[0];
    const int*   mask = (const int*)d_in[1];
    const float* Wq = (const float*)d_in[2];  const float* bq = (const float*)d_in[3];
    const float* Wk = (const float*)d_in[4];  const float* bk = (const float*)d_in[5];
    const float* Wv = (const float*)d_in[6];  const float* bv = (const float*)d_in[7];
    const float* Wo = (const float*)d_in[8];  const float* bo = (const float*)d_in[9];
    const float* W1 = (const float*)d_in[10]; const float* b1 = (const float*)d_in[11];
    const float* W2 = (const float*)d_in[12]; const float* b2 = (const float*)d_in[13];
    const float* ga = (const float*)d_in[14]; const float* ba = (const float*)d_in[15];
    const float* gf = (const float*)d_in[16]; const float* bf = (const float*)d_in[17];
    float* out = (float*)d_out;

    float *nx, *x1, *qkv, *hb, *wqkv, *bqkv, *wo, *w1, *w2;
    cudaGetSymbolAddress((void**)&nx,   g_bufA);
    cudaGetSymbolAddress((void**)&x1,   g_x1);
    cudaGetSymbolAddress((void**)&qkv,  g_qkv);
    cudaGetSymbolAddress((void**)&hb,   g_h);
    cudaGetSymbolAddress((void**)&wqkv, g_wqkv);
    cudaGetSymbolAddress((void**)&bqkv, g_bqkv);
    cudaGetSymbolAddress((void**)&wo,   g_wo);
    cudaGetSymbolAddress((void**)&w1,   g_w1);
    cudaGetSymbolAddress((void**)&w2,   g_w2);

    cudaFuncSetAttribute(gemm_mma<EPI_NONE>,
                         cudaFuncAttributeMaxDynamicSharedMemorySize, GEMM_SMEM);
    cudaFuncSetAttribute(gemm_mma<EPI_RES>,
                         cudaFuncAttributeMaxDynamicSharedMemorySize, GEMM_SMEM);
    cudaFuncSetAttribute(gemm_mma<EPI_GELU>,
                         cudaFuncAttributeMaxDynamicSharedMemorySize, GEMM_SMEM);

    // 0: all weight cvt; 1: bias pack; 2: LN; 3: QKV GEMM (ncu slot 5 offset ok)
    cvt_all_kernel<<<CVT_TOTAL / 256, 256>>>(Wq, Wk, Wv, Wo, W1, W2,
                                             wqkv, wo, w1, w2);
    pack_bias_kernel<<<(D_ + 255) / 256, 256>>>(bq, bk, bv, bqkv);
    ln_kernel<1><<<ROWS, 256>>>(x, ga, ba, nx);

    dim3 gqkv(QKV_S / 128, ROWS / 128);
    gemm_mma<EPI_NONE><<<gqkv, 128, GEMM_SMEM>>>(ROWS, QKV_S, D_, nx, wqkv, bqkv,
                                                 nullptr, qkv);

    attn_mma<<<dim3(S_ / 128, H_, B_), 256>>>(qkv, mask, nx);

    dim3 g1(D_ / 128, ROWS / 128);
    gemm_mma<EPI_RES><<<g1, 128, GEMM_SMEM>>>(ROWS, D_, D_, nx, wo, bo, x, x1);

    ln_kernel<1><<<ROWS, 256>>>(x1, gf, bf, qkv);

    dim3 g2(DFF_ / 128, ROWS / 128);
    gemm_mma<EPI_GELU><<<g2, 128, GEMM_SMEM>>>(ROWS, DFF_, D_, qkv, w1, b1,
                                               nullptr, hb);

    gemm_mma<EPI_RES><<<g1, 128, GEMM_SMEM>>>(ROWS, D_, DFF_, hb, w2, b2, x1, out);
}

// round 10
// speedup vs baseline: 1.7540x; 1.7076x over previous
#include <cuda_runtime.h>
#include <cuda_fp16.h>
#include <cstdint>

#define B_   2
#define S_   2048
#define D_   1024
#define H_   16
#define DK_  64
#define DFF_ 4096
#define ROWS (B_*S_)     // 4096
#define QKV_S (3*D_)     // 3072

// ---------------- scratch (device globals; no allocations allowed) ----------
__device__ __half g_nxh [ROWS*D_];      // LN1 out
__device__ __half g_qkvh[ROWS*QKV_S];   // packed q|k|v
__device__ __half g_ctxh[ROWS*D_];      // attention context
__device__ float  g_x1  [ROWS*D_];      // x after attn residual (fp32)
__device__ __half g_nx2h[ROWS*D_];      // LN2 out
__device__ __half g_hh  [ROWS*DFF_];    // ffn hidden
// fp16 weights
__device__ __half g_wqkvh[3*D_*D_];
__device__ float  g_bqkv[3*D_];
__device__ __half g_woh[D_*D_];
__device__ __half g_w1h[DFF_*D_], g_w2h[D_*DFF_];

// ---------------- helpers ----------------------------------------------------
__device__ __forceinline__ uint32_t smem_u32(const void* p) {
    uint32_t a;
    asm("{ .reg .u64 t; cvta.to.shared.u64 t, %1; cvt.u32.u64 %0, t; }"
        : "=r"(a) : "l"(p));
    return a;
}
__device__ __forceinline__ void cp16(uint32_t dst, const void* src) {
    asm volatile("cp.async.cg.shared.global [%0], [%1], 16;"
                 :: "r"(dst), "l"(src) : "memory");
}
__device__ __forceinline__ void cp_commit() {
    asm volatile("cp.async.commit_group;" ::: "memory");
}
__device__ __forceinline__ void ldsm4(uint32_t* r, uint32_t addr) {
    asm volatile("ldmatrix.sync.aligned.m8n8.x4.shared.b16 {%0,%1,%2,%3}, [%4];"
                 : "=r"(r[0]), "=r"(r[1]), "=r"(r[2]), "=r"(r[3]) : "r"(addr));
}
// m16n8k16 fp16, fp32 accumulate
__device__ __forceinline__ void mma16h(float* c, const uint32_t* a,
                                       uint32_t b0, uint32_t b1) {
    asm volatile(
        "mma.sync.aligned.m16n8k16.row.col.f32.f16.f16.f32 "
        "{%0,%1,%2,%3}, {%4,%5,%6,%7}, {%8,%9}, {%0,%1,%2,%3};"
        : "+f"(c[0]), "+f"(c[1]), "+f"(c[2]), "+f"(c[3])
        : "r"(a[0]), "r"(a[1]), "r"(a[2]), "r"(a[3]), "r"(b0), "r"(b1));
}
// pack two f32 -> f16x2 (lo = first arg)
__device__ __forceinline__ uint32_t f16pk(float lo, float hi) {
    uint32_t r;
    asm("cvt.rn.f16x2.f32 %0, %1, %2;" : "=r"(r) : "f"(hi), "f"(lo));
    return r;
}

// ---------------- fused weight conversion (all fp16) -------------------------
#define NDD4 (D_*D_/4)
#define NDF4 (DFF_*D_/4)
#define CVT_TOTAL (4*NDD4 + 2*NDF4)

__global__ __launch_bounds__(256) void cvt_all_kernel(
    const float* __restrict__ Wq, const float* __restrict__ Wk,
    const float* __restrict__ Wv, const float* __restrict__ Wo,
    const float* __restrict__ W1, const float* __restrict__ W2,
    __half* __restrict__ wqkv, __half* __restrict__ wo,
    __half* __restrict__ w1h, __half* __restrict__ w2h)
{
    const int i = blockIdx.x * 256 + threadIdx.x;
    const float4* src; __half* dst; int si, off;
    if (i < NDD4)             { src = (const float4*)Wq; si = i;               dst = wqkv; off = i; }
    else if (i < 2*NDD4)      { src = (const float4*)Wk; si = i - NDD4;        dst = wqkv; off = i; }
    else if (i < 3*NDD4)      { src = (const float4*)Wv; si = i - 2*NDD4;      dst = wqkv; off = i; }
    else if (i < 4*NDD4)      { src = (const float4*)Wo; si = i - 3*NDD4;      dst = wo;   off = si; }
    else if (i < 4*NDD4+NDF4) { src = (const float4*)W1; si = i - 4*NDD4;      dst = w1h;  off = si; }
    else                      { src = (const float4*)W2; si = i - 4*NDD4-NDF4; dst = w2h;  off = si; }
    float4 v = src[si];
    uint2 o;
    o.x = f16pk(v.x, v.y);
    o.y = f16pk(v.z, v.w);
    *(uint2*)&dst[(size_t)off * 4] = o;
}

__global__ __launch_bounds__(256) void pack_bias_kernel(
    const float* __restrict__ a, const float* __restrict__ b,
    const float* __restrict__ c, float* __restrict__ o)
{
    int i = blockIdx.x * 256 + threadIdx.x;
    if (i < D_) { o[i] = a[i]; o[D_ + i] = b[i]; o[2*D_ + i] = c[i]; }
}

// ---------------- LayerNorm (fp16 out) ----------------------------------------
__global__ __launch_bounds__(256) void ln_kernel(
    const float* __restrict__ x, const float* __restrict__ g,
    const float* __restrict__ bta, __half* __restrict__ out)
{
    const int row = blockIdx.x;
    const int t   = threadIdx.x;
    const float4* xr = (const float4*)(x + (size_t)row * D_);
    float4 v = xr[t];
    float s  = v.x + v.y + v.z + v.w;
    float s2 = v.x*v.x + v.y*v.y + v.z*v.z + v.w*v.w;
    #pragma unroll
    for (int o = 16; o > 0; o >>= 1) {
        s  += __shfl_xor_sync(0xffffffffu, s,  o);
        s2 += __shfl_xor_sync(0xffffffffu, s2, o);
    }
    __shared__ float rs[8], rs2[8];
    const int w = t >> 5;
    if ((t & 31) == 0) { rs[w] = s; rs2[w] = s2; }
    __syncthreads();
    s = 0.f; s2 = 0.f;
    #pragma unroll
    for (int i = 0; i < 8; i++) { s += rs[i]; s2 += rs2[i]; }
    const float mu   = s * (1.0f / D_);
    const float var  = s2 * (1.0f / D_) - mu * mu;
    const float rstd = rsqrtf(var + 1e-5f);
    float4 gg = ((const float4*)g)[t];
    float4 bb = ((const float4*)bta)[t];
    uint2 o;
    o.x = f16pk((v.x - mu) * rstd * gg.x + bb.x,
                (v.y - mu) * rstd * gg.y + bb.y);
    o.y = f16pk((v.z - mu) * rstd * gg.z + bb.z,
                (v.w - mu) * rstd * gg.w + bb.w);
    *(uint2*)(out + (size_t)row * D_ + t * 4) = o;
}

// ---------------- FP16 GEMM-NT: 4 warps, warp tile 64x64, K-tile 64 ----------
// A[M,K] fp16, Bw[N,K] fp16.
// EPI_H16 -> fp16 out; EPI_RES -> fp32 out + fp32 residual; EPI_G16 -> gelu fp16
enum { EPI_H16 = 0, EPI_RES = 1, EPI_G16 = 2 };
#define STAGES 3
#define STAGE_BYTES 32768
#define GEMM_SMEM (STAGES * STAGE_BYTES)   // 96 KB

template <int EPI>
__global__ __launch_bounds__(128, 2) void gemm_f16(
    int M, int N, int K,
    const __half* __restrict__ A, const __half* __restrict__ Bw,
    const float* __restrict__ bias, const float* __restrict__ resid,
    void* __restrict__ Cout)
{
    extern __shared__ float sm[];
    const int tid  = threadIdx.x;
    const int lane = tid & 31;
    const int wid  = tid >> 5;
    const int wm = wid & 1;
    const int wn = wid >> 1;
    const int brow = blockIdx.y * 128;
    const int bcol = blockIdx.x * 128;
    const int T = K >> 6;           // k-tiles of 64 fp16

    const uint32_t smb = smem_u32(sm);

    int am[8], akq[8];
    #pragma unroll
    for (int p = 0; p < 8; p++) {
        const int c = tid + 128 * p;
        am[p]  = c >> 3;          // row
        akq[p] = c & 7;           // 16B chunk (8 fp16)
    }

    float acc[4][8][4];
    #pragma unroll
    for (int mi = 0; mi < 4; mi++)
        #pragma unroll
        for (int ni = 0; ni < 8; ni++)
            #pragma unroll
            for (int e = 0; e < 4; e++) acc[mi][ni][e] = 0.f;

    auto issue = [&](int i, int stg) {
        const uint32_t dA = smb + (uint32_t)stg * STAGE_BYTES;
        const uint32_t dB = dA + 16384u;
        const int kbase = i * 64;
        #pragma unroll
        for (int p = 0; p < 8; p++) {
            const int m = am[p], kq = akq[p];
            const uint32_t doff = (uint32_t)(m * 128 + (((kq ^ (m & 7)) << 4)));
            cp16(dA + doff, A  + (size_t)(brow + m) * K + kbase + kq * 8);
            cp16(dB + doff, Bw + (size_t)(bcol + m) * K + kbase + kq * 8);
        }
        cp_commit();
    };

    // fragment lane addressing (16B chunk units, row stride 128B)
    const int a_r  = lane & 15;
    const int a_kq = lane >> 4;
    const int b_r  = (lane & 7) + ((lane >> 4) << 3);
    const int b_kq = (lane >> 3) & 1;
    uint32_t abase[4], axor[4], bbase[4], bxor[4];
    #pragma unroll
    for (int mi = 0; mi < 4; mi++) {
        const int row = wm * 64 + mi * 16 + a_r;
        abase[mi] = (uint32_t)(row * 128);
        axor[mi]  = (uint32_t)(row & 7);
    }
    #pragma unroll
    for (int g = 0; g < 4; g++) {
        const int row = wn * 64 + g * 16 + b_r;
        bbase[g] = (uint32_t)(16384 + row * 128);
        bxor[g]  = (uint32_t)(row & 7);
    }

    issue(0, 0);
    issue(1, 1);

    int stg = 0;
    for (int i = 0; i < T; i++) {
        if (i < T - 1) asm volatile("cp.async.wait_group 1;" ::: "memory");
        else           asm volatile("cp.async.wait_group 0;" ::: "memory");
        __syncthreads();

        if (i + 2 < T) {
            int nstg = stg + 2; if (nstg >= STAGES) nstg -= STAGES;
            issue(i + 2, nstg);
        }

        const uint32_t bufb = smb + (uint32_t)stg * STAGE_BYTES;

        #pragma unroll
        for (int s = 0; s < 4; s++) {     // 4 x k16
            const uint32_t k0q = (uint32_t)(s * 2);
            uint32_t af[4][4], bfr[4][4];
            #pragma unroll
            for (int mi = 0; mi < 4; mi++)
                ldsm4(af[mi], bufb + abase[mi] + (((k0q + a_kq) ^ axor[mi]) << 4));
            #pragma unroll
            for (int g = 0; g < 4; g++)
                ldsm4(bfr[g], bufb + bbase[g] + (((k0q + b_kq) ^ bxor[g]) << 4));
            #pragma unroll
            for (int mi = 0; mi < 4; mi++)
                #pragma unroll
                for (int ni = 0; ni < 8; ni++)
                    mma16h(acc[mi][ni], af[mi],
                           bfr[ni >> 1][(ni & 1) * 2],
                           bfr[ni >> 1][(ni & 1) * 2 + 1]);
        }
        if (++stg == STAGES) stg = 0;
    }

    #pragma unroll
    for (int mi = 0; mi < 4; mi++) {
        #pragma unroll
        for (int ni = 0; ni < 8; ni++) {
            const int r0  = brow + wm * 64 + mi * 16 + (lane >> 2);
            const int col = bcol + wn * 64 + ni * 8 + 2 * (lane & 3);
            const float b0 = bias[col], b1 = bias[col + 1];
            float v[4] = { acc[mi][ni][0] + b0, acc[mi][ni][1] + b1,
                           acc[mi][ni][2] + b0, acc[mi][ni][3] + b1 };
            if (EPI == EPI_RES) {
                float* C = (float*)Cout;
                const float2 x0 = *(const float2*)&resid[(size_t)r0 * N + col];
                const float2 x1 = *(const float2*)&resid[(size_t)(r0 + 8) * N + col];
                v[0] += x0.x; v[1] += x0.y; v[2] += x1.x; v[3] += x1.y;
                *(float2*)&C[(size_t)r0 * N + col]       = make_float2(v[0], v[1]);
                *(float2*)&C[(size_t)(r0 + 8) * N + col] = make_float2(v[2], v[3]);
            } else {
                if (EPI == EPI_G16) {
                    #pragma unroll
                    for (int e = 0; e < 4; e++)
                        v[e] = 0.5f * v[e] *
                               (1.0f + erff(v[e] * 0.70710678118654752f));
                }
                __half* C = (__half*)Cout;
                *(uint32_t*)&C[(size_t)r0 * N + col]       = f16pk(v[0], v[1]);
                *(uint32_t*)&C[(size_t)(r0 + 8) * N + col] = f16pk(v[2], v[3]);
            }
        }
    }
}

// ---------------- fp16 tensor-core flash attention ----------------------------
// grid (S/128, H, B), 256 threads; QK^T and P·V both m16n8k16 fp16.
__global__ __launch_bounds__(256) void attn_mma(
    const __half* __restrict__ QKV, const int* __restrict__ mask,
    __half* __restrict__ O)
{
    __shared__ __align__(16) __half Ks[64][72];   // [key][dk]
    __shared__ __align__(16) __half Vs[64][72];   // [dk][key]

    const int b = blockIdx.z, h = blockIdx.y;
    const int tid = threadIdx.x, lane = tid & 31, wid = tid >> 5;
    const int gp = lane >> 2, tg = lane & 3;
    const int qrow0 = blockIdx.x * 128 + wid * 16 + gp;

    const __half* Qb = QKV + (size_t)(b * S_) * QKV_S + h * DK_;
    const __half* Kb = Qb + D_;
    const __half* Vb = Qb + 2 * D_;

    // Q fragments: 4 k16 steps x 4 regs (fp16 pairs straight from global)
    uint32_t qf[4][4];
    {
        const __half* q0p = Qb + (size_t)qrow0 * QKV_S;
        const __half* q1p = q0p + (size_t)8 * QKV_S;
        #pragma unroll
        for (int s = 0; s < 4; s++) {
            qf[s][0] = *(const uint32_t*)&q0p[16*s + 2*tg];
            qf[s][1] = *(const uint32_t*)&q1p[16*s + 2*tg];
            qf[s][2] = *(const uint32_t*)&q0p[16*s + 2*tg + 8];
            qf[s][3] = *(const uint32_t*)&q1p[16*s + 2*tg + 8];
        }
    }

    float oa[8][4];
    #pragma unroll
    for (int j = 0; j < 8; j++)
        #pragma unroll
        for (int e = 0; e < 4; e++) oa[j][e] = 0.f;
    float m0c = -1e30f, m1c = -1e30f, l0 = 0.f, l1 = 0.f;

    const int* mr0 = mask + ((size_t)(b * S_ + qrow0)) * S_;
    const int* mr1 = mr0 + (size_t)8 * S_;

    for (int kt = 0; kt < S_; kt += 64) {
        // stage K (direct) and V (transposed), both fp16
        #pragma unroll
        for (int p = 0; p < 2; p++) {
            const int c = tid + 256 * p;          // 0..511 uint4 slots
            const int key = c >> 3, ch = (c & 7) * 8;
            const size_t gk = (size_t)(kt + key) * QKV_S + ch;
            uint4 kv = *(const uint4*)&Kb[gk];
            *(uint4*)&Ks[key][ch] = kv;
            uint4 vv = *(const uint4*)&Vb[gk];
            const __half* vh = (const __half*)&vv;
            #pragma unroll
            for (int e = 0; e < 8; e++) Vs[ch + e][key] = vh[e];
        }
        __syncthreads();

        // S = Q·K^T  (8 key n-tiles x 4 k16 steps)
        float sc[8][4];
        #pragma unroll
        for (int j = 0; j < 8; j++)
            #pragma unroll
            for (int e = 0; e < 4; e++) sc[j][e] = 0.f;
        #pragma unroll
        for (int s = 0; s < 4; s++) {
            #pragma unroll
            for (int j = 0; j < 8; j++) {
                const uint32_t kb0 = *(const uint32_t*)&Ks[8*j + gp][16*s + 2*tg];
                const uint32_t kb1 = *(const uint32_t*)&Ks[8*j + gp][16*s + 2*tg + 8];
                mma16h(sc[j], qf[s], kb0, kb1);
            }
        }

        // scale (exact) + mask (-10000.0 semantics)
        #pragma unroll
        for (int j = 0; j < 8; j++) {
            const int2 mm0 = *(const int2*)&mr0[kt + 8*j + 2*tg];
            const int2 mm1 = *(const int2*)&mr1[kt + 8*j + 2*tg];
            sc[j][0] = mm0.x ? -10000.0f : sc[j][0] * 0.125f;
            sc[j][1] = mm0.y ? -10000.0f : sc[j][1] * 0.125f;
            sc[j][2] = mm1.x ? -10000.0f : sc[j][2] * 0.125f;
            sc[j][3] = mm1.y ? -10000.0f : sc[j][3] * 0.125f;
        }

        // online softmax
        float t0 = -1e30f, t1 = -1e30f;
        #pragma unroll
        for (int j = 0; j < 8; j++) {
            t0 = fmaxf(t0, fmaxf(sc[j][0], sc[j][1]));
            t1 = fmaxf(t1, fmaxf(sc[j][2], sc[j][3]));
        }
        t0 = fmaxf(t0, __shfl_xor_sync(0xffffffffu, t0, 1));
        t0 = fmaxf(t0, __shfl_xor_sync(0xffffffffu, t0, 2));
        t1 = fmaxf(t1, __shfl_xor_sync(0xffffffffu, t1, 1));
        t1 = fmaxf(t1, __shfl_xor_sync(0xffffffffu, t1, 2));
        const float mn0 = fmaxf(m0c, t0), mn1 = fmaxf(m1c, t1);
        const float cr0 = __expf(m0c - mn0), cr1 = __expf(m1c - mn1);
        float ps0 = 0.f, ps1 = 0.f;
        #pragma unroll
        for (int j = 0; j < 8; j++) {
            sc[j][0] = __expf(sc[j][0] - mn0); ps0 += sc[j][0];
            sc[j][1] = __expf(sc[j][1] - mn0); ps0 += sc[j][1];
            sc[j][2] = __expf(sc[j][2] - mn1); ps1 += sc[j][2];
            sc[j][3] = __expf(sc[j][3] - mn1); ps1 += sc[j][3];
        }
        ps0 += __shfl_xor_sync(0xffffffffu, ps0, 1);
        ps0 += __shfl_xor_sync(0xffffffffu, ps0, 2);
        ps1 += __shfl_xor_sync(0xffffffffu, ps1, 1);
        ps1 += __shfl_xor_sync(0xffffffffu, ps1, 2);
        l0 = l0 * cr0 + ps0; m0c = mn0;
        l1 = l1 * cr1 + ps1; m1c = mn1;
        #pragma unroll
        for (int j = 0; j < 8; j++) {
            oa[j][0] *= cr0; oa[j][1] *= cr0;
            oa[j][2] *= cr1; oa[j][3] *= cr1;
        }

        // P (C layout) -> fp16 A fragments (layout identity, zero shuffles)
        uint32_t pa[4][4];
        #pragma unroll
        for (int t = 0; t < 4; t++) {
            pa[t][0] = f16pk(sc[2*t][0],     sc[2*t][1]);
            pa[t][1] = f16pk(sc[2*t][2],     sc[2*t][3]);
            pa[t][2] = f16pk(sc[2*t + 1][0], sc[2*t + 1][1]);
            pa[t][3] = f16pk(sc[2*t + 1][2], sc[2*t + 1][3]);
        }

        // O += P·V  (8 dk n-tiles x 4 key k16-tiles)
        #pragma unroll
        for (int j = 0; j < 8; j++) {
            #pragma unroll
            for (int t = 0; t < 4; t++) {
                const uint32_t vb0 =
                    *(const uint32_t*)&Vs[8*j + gp][16*t + 2*tg];
                const uint32_t vb1 =
                    *(const uint32_t*)&Vs[8*j + gp][16*t + 8 + 2*tg];
                mma16h(oa[j], pa[t], vb0, vb1);
            }
        }
        __syncthreads();
    }

    const float inv0 = 1.0f / l0, inv1 = 1.0f / l1;
    __half* o0 = O + ((size_t)(b * S_ + qrow0)) * D_ + h * DK_;
    __half* o1 = o0 + (size_t)8 * D_;
    #pragma unroll
    for (int j = 0; j < 8; j++) {
        *(uint32_t*)&o0[8*j + 2*tg] = f16pk(oa[j][0] * inv0, oa[j][1] * inv0);
        *(uint32_t*)&o1[8*j + 2*tg] = f16pk(oa[j][2] * inv1, oa[j][3] * inv1);
    }
}

// ---------------- launcher ----------------------------------------------------
extern "C" void kernel_launch(void* const* d_in, const int* in_sizes, int n_in,
                              void* d_out, int out_size)
{
    const float* x  = (const float*)d_in[0];
    const int*   mask = (const int*)d_in[1];
    const float* Wq = (const float*)d_in[2];  const float* bq = (const float*)d_in[3];
    const float* Wk = (const float*)d_in[4];  const float* bk = (const float*)d_in[5];
    const float* Wv = (const float*)d_in[6];  const float* bv = (const float*)d_in[7];
    const float* Wo = (const float*)d_in[8];  const float* bo = (const float*)d_in[9];
    const float* W1 = (const float*)d_in[10]; const float* b1 = (const float*)d_in[11];
    const float* W2 = (const float*)d_in[12]; const float* b2 = (const float*)d_in[13];
    const float* ga = (const float*)d_in[14]; const float* ba = (const float*)d_in[15];
    const float* gf = (const float*)d_in[16]; const float* bf = (const float*)d_in[17];
    float* out = (float*)d_out;

    __half *nxh, *qkvh, *ctxh, *nx2h, *hh, *wqkvh, *woh, *w1h, *w2h;
    float *x1, *bqkv;
    cudaGetSymbolAddress((void**)&nxh,   g_nxh);
    cudaGetSymbolAddress((void**)&qkvh,  g_qkvh);
    cudaGetSymbolAddress((void**)&ctxh,  g_ctxh);
    cudaGetSymbolAddress((void**)&x1,    g_x1);
    cudaGetSymbolAddress((void**)&nx2h,  g_nx2h);
    cudaGetSymbolAddress((void**)&hh,    g_hh);
    cudaGetSymbolAddress((void**)&wqkvh, g_wqkvh);
    cudaGetSymbolAddress((void**)&bqkv,  g_bqkv);
    cudaGetSymbolAddress((void**)&woh,   g_woh);
    cudaGetSymbolAddress((void**)&w1h,   g_w1h);
    cudaGetSymbolAddress((void**)&w2h,   g_w2h);

    cudaFuncSetAttribute(gemm_f16<EPI_H16>,
                         cudaFuncAttributeMaxDynamicSharedMemorySize, GEMM_SMEM);
    cudaFuncSetAttribute(gemm_f16<EPI_RES>,
                         cudaFuncAttributeMaxDynamicSharedMemorySize, GEMM_SMEM);
    cudaFuncSetAttribute(gemm_f16<EPI_G16>,
                         cudaFuncAttributeMaxDynamicSharedMemorySize, GEMM_SMEM);

    // 0: weight cvt; 1: bias pack; 2: LN1; 3: QKV GEMM; 4: attn; ...
    cvt_all_kernel<<<CVT_TOTAL / 256, 256>>>(Wq, Wk, Wv, Wo, W1, W2,
                                             wqkvh, woh, w1h, w2h);
    pack_bias_kernel<<<(D_ + 255) / 256, 256>>>(bq, bk, bv, bqkv);
    ln_kernel<<<ROWS, 256>>>(x, ga, ba, nxh);

    dim3 gqkv(QKV_S / 128, ROWS / 128);
    gemm_f16<EPI_H16><<<gqkv, 128, GEMM_SMEM>>>(ROWS, QKV_S, D_, nxh, wqkvh,
                                                bqkv, nullptr, qkvh);

    attn_mma<<<dim3(S_ / 128, H_, B_), 256>>>(qkvh, mask, ctxh);

    dim3 g1(D_ / 128, ROWS / 128);
    gemm_f16<EPI_RES><<<g1, 128, GEMM_SMEM>>>(ROWS, D_, D_, ctxh, woh, bo, x, x1);

    ln_kernel<<<ROWS, 256>>>(x1, gf, bf, nx2h);

    dim3 g2(DFF_ / 128, ROWS / 128);
    gemm_f16<EPI_G16><<<g2, 128, GEMM_SMEM>>>(ROWS, DFF_, D_, nx2h, w1h, b1,
                                              nullptr, hh);

    gemm_f16<EPI_RES><<<g1, 128, GEMM_SMEM>>>(ROWS, D_, DFF_, hh, w2h, b2, x1, out);
}

// round 11
// speedup vs baseline: 2.0924x; 1.1930x over previous
#include <cuda_runtime.h>
#include <cuda_fp16.h>
#include <cstdint>

#define B_   2
#define S_   2048
#define D_   1024
#define H_   16
#define DK_  64
#define DFF_ 4096
#define ROWS (B_*S_)     // 4096
#define QKV_S (3*D_)     // 3072

// ---------------- scratch (device globals; no allocations allowed) ----------
__device__ __half g_nxh [ROWS*D_];      // LN1 out
__device__ __half g_qkvh[ROWS*QKV_S];   // packed q|k|v
__device__ __half g_ctxh[ROWS*D_];      // attention context
__device__ float  g_x1  [ROWS*D_];      // x after attn residual (fp32)
__device__ __half g_nx2h[ROWS*D_];      // LN2 out
__device__ __half g_hh  [ROWS*DFF_];    // ffn hidden
// fp16 weights
__device__ __half g_wqkvh[3*D_*D_];
__device__ float  g_bqkv[3*D_];
__device__ __half g_woh[D_*D_];
__device__ __half g_w1h[DFF_*D_], g_w2h[D_*DFF_];

// ---------------- helpers ----------------------------------------------------
__device__ __forceinline__ uint32_t smem_u32(const void* p) {
    uint32_t a;
    asm("{ .reg .u64 t; cvta.to.shared.u64 t, %1; cvt.u32.u64 %0, t; }"
        : "=r"(a) : "l"(p));
    return a;
}
__device__ __forceinline__ void cp16(uint32_t dst, const void* src) {
    asm volatile("cp.async.cg.shared.global [%0], [%1], 16;"
                 :: "r"(dst), "l"(src) : "memory");
}
__device__ __forceinline__ void cp_commit() {
    asm volatile("cp.async.commit_group;" ::: "memory");
}
__device__ __forceinline__ void ldsm4(uint32_t* r, uint32_t addr) {
    asm volatile("ldmatrix.sync.aligned.m8n8.x4.shared.b16 {%0,%1,%2,%3}, [%4];"
                 : "=r"(r[0]), "=r"(r[1]), "=r"(r[2]), "=r"(r[3]) : "r"(addr));
}
__device__ __forceinline__ void ldsm4t(uint32_t* r, uint32_t addr) {
    asm volatile("ldmatrix.sync.aligned.m8n8.x4.trans.shared.b16 {%0,%1,%2,%3}, [%4];"
                 : "=r"(r[0]), "=r"(r[1]), "=r"(r[2]), "=r"(r[3]) : "r"(addr));
}
// m16n8k16 fp16, fp32 accumulate
__device__ __forceinline__ void mma16h(float* c, const uint32_t* a,
                                       uint32_t b0, uint32_t b1) {
    asm volatile(
        "mma.sync.aligned.m16n8k16.row.col.f32.f16.f16.f32 "
        "{%0,%1,%2,%3}, {%4,%5,%6,%7}, {%8,%9}, {%0,%1,%2,%3};"
        : "+f"(c[0]), "+f"(c[1]), "+f"(c[2]), "+f"(c[3])
        : "r"(a[0]), "r"(a[1]), "r"(a[2]), "r"(a[3]), "r"(b0), "r"(b1));
}
// pack two f32 -> f16x2 (lo = first arg)
__device__ __forceinline__ uint32_t f16pk(float lo, float hi) {
    uint32_t r;
    asm("cvt.rn.f16x2.f32 %0, %1, %2;" : "=r"(r) : "f"(hi), "f"(lo));
    return r;
}

// ---------------- fused weight conversion (all fp16) -------------------------
#define NDD4 (D_*D_/4)
#define NDF4 (DFF_*D_/4)
#define CVT_TOTAL (4*NDD4 + 2*NDF4)

__global__ __launch_bounds__(256) void cvt_all_kernel(
    const float* __restrict__ Wq, const float* __restrict__ Wk,
    const float* __restrict__ Wv, const float* __restrict__ Wo,
    const float* __restrict__ W1, const float* __restrict__ W2,
    __half* __restrict__ wqkv, __half* __restrict__ wo,
    __half* __restrict__ w1h, __half* __restrict__ w2h)
{
    const int i = blockIdx.x * 256 + threadIdx.x;
    const float4* src; __half* dst; int si, off;
    if (i < NDD4)             { src = (const float4*)Wq; si = i;               dst = wqkv; off = i; }
    else if (i < 2*NDD4)      { src = (const float4*)Wk; si = i - NDD4;        dst = wqkv; off = i; }
    else if (i < 3*NDD4)      { src = (const float4*)Wv; si = i - 2*NDD4;      dst = wqkv; off = i; }
    else if (i < 4*NDD4)      { src = (const float4*)Wo; si = i - 3*NDD4;      dst = wo;   off = si; }
    else if (i < 4*NDD4+NDF4) { src = (const float4*)W1; si = i - 4*NDD4;      dst = w1h;  off = si; }
    else                      { src = (const float4*)W2; si = i - 4*NDD4-NDF4; dst = w2h;  off = si; }
    float4 v = src[si];
    uint2 o;
    o.x = f16pk(v.x, v.y);
    o.y = f16pk(v.z, v.w);
    *(uint2*)&dst[(size_t)off * 4] = o;
}

__global__ __launch_bounds__(256) void pack_bias_kernel(
    const float* __restrict__ a, const float* __restrict__ b,
    const float* __restrict__ c, float* __restrict__ o)
{
    int i = blockIdx.x * 256 + threadIdx.x;
    if (i < D_) { o[i] = a[i]; o[D_ + i] = b[i]; o[2*D_ + i] = c[i]; }
}

// ---------------- LayerNorm (fp16 out) ----------------------------------------
__global__ __launch_bounds__(256) void ln_kernel(
    const float* __restrict__ x, const float* __restrict__ g,
    const float* __restrict__ bta, __half* __restrict__ out)
{
    const int row = blockIdx.x;
    const int t   = threadIdx.x;
    const float4* xr = (const float4*)(x + (size_t)row * D_);
    float4 v = xr[t];
    float s  = v.x + v.y + v.z + v.w;
    float s2 = v.x*v.x + v.y*v.y + v.z*v.z + v.w*v.w;
    #pragma unroll
    for (int o = 16; o > 0; o >>= 1) {
        s  += __shfl_xor_sync(0xffffffffu, s,  o);
        s2 += __shfl_xor_sync(0xffffffffu, s2, o);
    }
    __shared__ float rs[8], rs2[8];
    const int w = t >> 5;
    if ((t & 31) == 0) { rs[w] = s; rs2[w] = s2; }
    __syncthreads();
    s = 0.f; s2 = 0.f;
    #pragma unroll
    for (int i = 0; i < 8; i++) { s += rs[i]; s2 += rs2[i]; }
    const float mu   = s * (1.0f / D_);
    const float var  = s2 * (1.0f / D_) - mu * mu;
    const float rstd = rsqrtf(var + 1e-5f);
    float4 gg = ((const float4*)g)[t];
    float4 bb = ((const float4*)bta)[t];
    uint2 o;
    o.x = f16pk((v.x - mu) * rstd * gg.x + bb.x,
                (v.y - mu) * rstd * gg.y + bb.y);
    o.y = f16pk((v.z - mu) * rstd * gg.z + bb.z,
                (v.w - mu) * rstd * gg.w + bb.w);
    *(uint2*)(out + (size_t)row * D_ + t * 4) = o;
}

// ---------------- FP16 GEMM-NT: 4 warps, warp tile 64x64, K-tile 64 ----------
enum { EPI_H16 = 0, EPI_RES = 1, EPI_G16 = 2 };
#define STAGES 3
#define STAGE_BYTES 32768
#define GEMM_SMEM (STAGES * STAGE_BYTES)   // 96 KB

template <int EPI>
__global__ __launch_bounds__(128, 2) void gemm_f16(
    int M, int N, int K,
    const __half* __restrict__ A, const __half* __restrict__ Bw,
    const float* __restrict__ bias, const float* __restrict__ resid,
    void* __restrict__ Cout)
{
    extern __shared__ float sm[];
    const int tid  = threadIdx.x;
    const int lane = tid & 31;
    const int wid  = tid >> 5;
    const int wm = wid & 1;
    const int wn = wid >> 1;
    const int brow = blockIdx.y * 128;
    const int bcol = blockIdx.x * 128;
    const int T = K >> 6;

    const uint32_t smb = smem_u32(sm);

    int am[8], akq[8];
    #pragma unroll
    for (int p = 0; p < 8; p++) {
        const int c = tid + 128 * p;
        am[p]  = c >> 3;
        akq[p] = c & 7;
    }

    float acc[4][8][4];
    #pragma unroll
    for (int mi = 0; mi < 4; mi++)
        #pragma unroll
        for (int ni = 0; ni < 8; ni++)
            #pragma unroll
            for (int e = 0; e < 4; e++) acc[mi][ni][e] = 0.f;

    auto issue = [&](int i, int stg) {
        const uint32_t dA = smb + (uint32_t)stg * STAGE_BYTES;
        const uint32_t dB = dA + 16384u;
        const int kbase = i * 64;
        #pragma unroll
        for (int p = 0; p < 8; p++) {
            const int m = am[p], kq = akq[p];
            const uint32_t doff = (uint32_t)(m * 128 + (((kq ^ (m & 7)) << 4)));
            cp16(dA + doff, A  + (size_t)(brow + m) * K + kbase + kq * 8);
            cp16(dB + doff, Bw + (size_t)(bcol + m) * K + kbase + kq * 8);
        }
        cp_commit();
    };

    const int a_r  = lane & 15;
    const int a_kq = lane >> 4;
    const int b_r  = (lane & 7) + ((lane >> 4) << 3);
    const int b_kq = (lane >> 3) & 1;
    uint32_t abase[4], axor[4], bbase[4], bxor[4];
    #pragma unroll
    for (int mi = 0; mi < 4; mi++) {
        const int row = wm * 64 + mi * 16 + a_r;
        abase[mi] = (uint32_t)(row * 128);
        axor[mi]  = (uint32_t)(row & 7);
    }
    #pragma unroll
    for (int g = 0; g < 4; g++) {
        const int row = wn * 64 + g * 16 + b_r;
        bbase[g] = (uint32_t)(16384 + row * 128);
        bxor[g]  = (uint32_t)(row & 7);
    }

    issue(0, 0);
    issue(1, 1);

    int stg = 0;
    for (int i = 0; i < T; i++) {
        if (i < T - 1) asm volatile("cp.async.wait_group 1;" ::: "memory");
        else           asm volatile("cp.async.wait_group 0;" ::: "memory");
        __syncthreads();

        if (i + 2 < T) {
            int nstg = stg + 2; if (nstg >= STAGES) nstg -= STAGES;
            issue(i + 2, nstg);
        }

        const uint32_t bufb = smb + (uint32_t)stg * STAGE_BYTES;

        #pragma unroll
        for (int s = 0; s < 4; s++) {
            const uint32_t k0q = (uint32_t)(s * 2);
            uint32_t af[4][4], bfr[4][4];
            #pragma unroll
            for (int mi = 0; mi < 4; mi++)
                ldsm4(af[mi], bufb + abase[mi] + (((k0q + a_kq) ^ axor[mi]) << 4));
            #pragma unroll
            for (int g = 0; g < 4; g++)
                ldsm4(bfr[g], bufb + bbase[g] + (((k0q + b_kq) ^ bxor[g]) << 4));
            #pragma unroll
            for (int mi = 0; mi < 4; mi++)
                #pragma unroll
                for (int ni = 0; ni < 8; ni++)
                    mma16h(acc[mi][ni], af[mi],
                           bfr[ni >> 1][(ni & 1) * 2],
                           bfr[ni >> 1][(ni & 1) * 2 + 1]);
        }
        if (++stg == STAGES) stg = 0;
    }

    #pragma unroll
    for (int mi = 0; mi < 4; mi++) {
        #pragma unroll
        for (int ni = 0; ni < 8; ni++) {
            const int r0  = brow + wm * 64 + mi * 16 + (lane >> 2);
            const int col = bcol + wn * 64 + ni * 8 + 2 * (lane & 3);
            const float b0 = bias[col], b1 = bias[col + 1];
            float v[4] = { acc[mi][ni][0] + b0, acc[mi][ni][1] + b1,
                           acc[mi][ni][2] + b0, acc[mi][ni][3] + b1 };
            if (EPI == EPI_RES) {
                float* C = (float*)Cout;
                const float2 x0 = *(const float2*)&resid[(size_t)r0 * N + col];
                const float2 x1 = *(const float2*)&resid[(size_t)(r0 + 8) * N + col];
                v[0] += x0.x; v[1] += x0.y; v[2] += x1.x; v[3] += x1.y;
                *(float2*)&C[(size_t)r0 * N + col]       = make_float2(v[0], v[1]);
                *(float2*)&C[(size_t)(r0 + 8) * N + col] = make_float2(v[2], v[3]);
            } else {
                if (EPI == EPI_G16) {
                    #pragma unroll
                    for (int e = 0; e < 4; e++)
                        v[e] = 0.5f * v[e] *
                               (1.0f + erff(v[e] * 0.70710678118654752f));
                }
                __half* C = (__half*)Cout;
                *(uint32_t*)&C[(size_t)r0 * N + col]       = f16pk(v[0], v[1]);
                *(uint32_t*)&C[(size_t)(r0 + 8) * N + col] = f16pk(v[2], v[3]);
            }
        }
    }
}

// ---------------- fp16 flash attention: cp.async + ldmatrix(+trans) ----------
// grid (S/128, H, B), 256 threads; K/V double-buffered; 1 barrier per tile.
#define ATT_ROWB 144            // 72 halves per row
#define ATT_BUFB (64 * ATT_ROWB) // 9216 bytes per matrix per stage

__global__ __launch_bounds__(256) void attn_mma(
    const __half* __restrict__ QKV, const int* __restrict__ mask,
    __half* __restrict__ O)
{
    __shared__ __align__(16) __half Ks[2][64][72];   // [buf][key][dk]
    __shared__ __align__(16) __half Vs[2][64][72];   // [buf][key][dk]

    const int b = blockIdx.z, h = blockIdx.y;
    const int tid = threadIdx.x, lane = tid & 31, wid = tid >> 5;
    const int gp = lane >> 2, tg = lane & 3;
    const int qrow0 = blockIdx.x * 128 + wid * 16 + gp;

    const __half* Qb = QKV + (size_t)(b * S_) * QKV_S + h * DK_;
    const __half* Kb = Qb + D_;
    const __half* Vb = Qb + 2 * D_;

    const uint32_t ksb = smem_u32(&Ks[0][0][0]);
    const uint32_t vsb = smem_u32(&Vs[0][0][0]);

    // cp.async slots: 512 chunks of 16B per matrix, 2 per thread
    int ckey[2], cch[2];
    #pragma unroll
    for (int p = 0; p < 2; p++) {
        const int c = tid + 256 * p;
        ckey[p] = c >> 3; cch[p] = c & 7;
    }
    auto issue_kv = [&](int kt, int buf) {
        const uint32_t kb = ksb + (uint32_t)buf * ATT_BUFB;
        const uint32_t vb = vsb + (uint32_t)buf * ATT_BUFB;
        #pragma unroll
        for (int p = 0; p < 2; p++) {
            const size_t g = (size_t)(kt + ckey[p]) * QKV_S + cch[p] * 8;
            const uint32_t off = (uint32_t)(ckey[p] * ATT_ROWB + cch[p] * 16);
            cp16(kb + off, Kb + g);
            cp16(vb + off, Vb + g);
        }
        cp_commit();
    };

    // ldsm lane-constant offsets
    // K (plain): row = 8*j0 + 8*((l>>4)&1) + (l&7); col = 16*s + 8*((l>>3)&1)
    const uint32_t kcon = (uint32_t)(((((lane >> 4) & 1) * 8 + (lane & 7)) * ATT_ROWB)
                                     + (((lane >> 3) & 1) * 8) * 2);
    // V (trans): row = 16*t + 8*((l>>3)&1) + (l&7); col = 8*(j0 + ((l>>4)&1))
    const uint32_t vcon = (uint32_t)((((lane >> 3) & 1) * 8 + (lane & 7)) * ATT_ROWB
                                     + (((lane >> 4) & 1) * 8) * 2);

    // Q fragments: 4 k16 steps x 4 regs
    uint32_t qf[4][4];
    {
        const __half* q0p = Qb + (size_t)qrow0 * QKV_S;
        const __half* q1p = q0p + (size_t)8 * QKV_S;
        #pragma unroll
        for (int s = 0; s < 4; s++) {
            qf[s][0] = *(const uint32_t*)&q0p[16*s + 2*tg];
            qf[s][1] = *(const uint32_t*)&q1p[16*s + 2*tg];
            qf[s][2] = *(const uint32_t*)&q0p[16*s + 2*tg + 8];
            qf[s][3] = *(const uint32_t*)&q1p[16*s + 2*tg + 8];
        }
    }

    float oa[8][4];
    #pragma unroll
    for (int j = 0; j < 8; j++)
        #pragma unroll
        for (int e = 0; e < 4; e++) oa[j][e] = 0.f;
    float m0c = -1e30f, m1c = -1e30f, l0 = 0.f, l1 = 0.f;

    const int* mr0 = mask + ((size_t)(b * S_ + qrow0)) * S_;
    const int* mr1 = mr0 + (size_t)8 * S_;

    issue_kv(0, 0);

    for (int it = 0; it < S_ / 64; it++) {
        asm volatile("cp.async.wait_group 0;" ::: "memory");
        __syncthreads();
        if (it + 1 < S_ / 64) issue_kv((it + 1) * 64, (it + 1) & 1);

        const uint32_t kbuf = ksb + (uint32_t)(it & 1) * ATT_BUFB;
        const uint32_t vbuf = vsb + (uint32_t)(it & 1) * ATT_BUFB;
        const int kt = it * 64;

        // S = Q·K^T
        float sc[8][4];
        #pragma unroll
        for (int j = 0; j < 8; j++)
            #pragma unroll
            for (int e = 0; e < 4; e++) sc[j][e] = 0.f;
        #pragma unroll
        for (int s = 0; s < 4; s++) {
            #pragma unroll
            for (int jj = 0; jj < 4; jj++) {
                uint32_t kf[4];
                ldsm4(kf, kbuf + (uint32_t)(jj * 2 * 8 * ATT_ROWB + s * 32) + kcon);
                mma16h(sc[2*jj],     qf[s], kf[0], kf[1]);
                mma16h(sc[2*jj + 1], qf[s], kf[2], kf[3]);
            }
        }

        // scale (exact) + mask
        #pragma unroll
        for (int j = 0; j < 8; j++) {
            const int2 mm0 = *(const int2*)&mr0[kt + 8*j + 2*tg];
            const int2 mm1 = *(const int2*)&mr1[kt + 8*j + 2*tg];
            sc[j][0] = mm0.x ? -10000.0f : sc[j][0] * 0.125f;
            sc[j][1] = mm0.y ? -10000.0f : sc[j][1] * 0.125f;
            sc[j][2] = mm1.x ? -10000.0f : sc[j][2] * 0.125f;
            sc[j][3] = mm1.y ? -10000.0f : sc[j][3] * 0.125f;
        }

        // online softmax
        float t0 = -1e30f, t1 = -1e30f;
        #pragma unroll
        for (int j = 0; j < 8; j++) {
            t0 = fmaxf(t0, fmaxf(sc[j][0], sc[j][1]));
            t1 = fmaxf(t1, fmaxf(sc[j][2], sc[j][3]));
        }
        t0 = fmaxf(t0, __shfl_xor_sync(0xffffffffu, t0, 1));
        t0 = fmaxf(t0, __shfl_xor_sync(0xffffffffu, t0, 2));
        t1 = fmaxf(t1, __shfl_xor_sync(0xffffffffu, t1, 1));
        t1 = fmaxf(t1, __shfl_xor_sync(0xffffffffu, t1, 2));
        const float mn0 = fmaxf(m0c, t0), mn1 = fmaxf(m1c, t1);
        const float cr0 = __expf(m0c - mn0), cr1 = __expf(m1c - mn1);
        float ps0 = 0.f, ps1 = 0.f;
        #pragma unroll
        for (int j = 0; j < 8; j++) {
            sc[j][0] = __expf(sc[j][0] - mn0); ps0 += sc[j][0];
            sc[j][1] = __expf(sc[j][1] - mn0); ps0 += sc[j][1];
            sc[j][2] = __expf(sc[j][2] - mn1); ps1 += sc[j][2];
            sc[j][3] = __expf(sc[j][3] - mn1); ps1 += sc[j][3];
        }
        ps0 += __shfl_xor_sync(0xffffffffu, ps0, 1);
        ps0 += __shfl_xor_sync(0xffffffffu, ps0, 2);
        ps1 += __shfl_xor_sync(0xffffffffu, ps1, 1);
        ps1 += __shfl_xor_sync(0xffffffffu, ps1, 2);
        l0 = l0 * cr0 + ps0; m0c = mn0;
        l1 = l1 * cr1 + ps1; m1c = mn1;
        #pragma unroll
        for (int j = 0; j < 8; j++) {
            oa[j][0] *= cr0; oa[j][1] *= cr0;
            oa[j][2] *= cr1; oa[j][3] *= cr1;
        }

        // P -> fp16 A fragments (layout identity)
        uint32_t pa[4][4];
        #pragma unroll
        for (int t = 0; t < 4; t++) {
            pa[t][0] = f16pk(sc[2*t][0],     sc[2*t][1]);
            pa[t][1] = f16pk(sc[2*t][2],     sc[2*t][3]);
            pa[t][2] = f16pk(sc[2*t + 1][0], sc[2*t + 1][1]);
            pa[t][3] = f16pk(sc[2*t + 1][2], sc[2*t + 1][3]);
        }

        // O += P·V via ldmatrix.trans fragments
        #pragma unroll
        for (int t = 0; t < 4; t++) {
            #pragma unroll
            for (int jj = 0; jj < 4; jj++) {
                uint32_t vf[4];
                ldsm4t(vf, vbuf + (uint32_t)(t * 16 * ATT_ROWB + jj * 2 * 16) + vcon);
                mma16h(oa[2*jj],     pa[t], vf[0], vf[1]);
                mma16h(oa[2*jj + 1], pa[t], vf[2], vf[3]);
            }
        }
    }

    const float inv0 = 1.0f / l0, inv1 = 1.0f / l1;
    __half* o0 = O + ((size_t)(b * S_ + qrow0)) * D_ + h * DK_;
    __half* o1 = o0 + (size_t)8 * D_;
    #pragma unroll
    for (int j = 0; j < 8; j++) {
        *(uint32_t*)&o0[8*j + 2*tg] = f16pk(oa[j][0] * inv0, oa[j][1] * inv0);
        *(uint32_t*)&o1[8*j + 2*tg] = f16pk(oa[j][2] * inv1, oa[j][3] * inv1);
    }
}

// ---------------- launcher ----------------------------------------------------
extern "C" void kernel_launch(void* const* d_in, const int* in_sizes, int n_in,
                              void* d_out, int out_size)
{
    const float* x  = (const float*)d_in[0];
    const int*   mask = (const int*)d_in[1];
    const float* Wq = (const float*)d_in[2];  const float* bq = (const float*)d_in[3];
    const float* Wk = (const float*)d_in[4];  const float* bk = (const float*)d_in[5];
    const float* Wv = (const float*)d_in[6];  const float* bv = (const float*)d_in[7];
    const float* Wo = (const float*)d_in[8];  const float* bo = (const float*)d_in[9];
    const float* W1 = (const float*)d_in[10]; const float* b1 = (const float*)d_in[11];
    const float* W2 = (const float*)d_in[12]; const float* b2 = (const float*)d_in[13];
    const float* ga = (const float*)d_in[14]; const float* ba = (const float*)d_in[15];
    const float* gf = (const float*)d_in[16]; const float* bf = (const float*)d_in[17];
    float* out = (float*)d_out;

    __half *nxh, *qkvh, *ctxh, *nx2h, *hh, *wqkvh, *woh, *w1h, *w2h;
    float *x1, *bqkv;
    cudaGetSymbolAddress((void**)&nxh,   g_nxh);
    cudaGetSymbolAddress((void**)&qkvh,  g_qkvh);
    cudaGetSymbolAddress((void**)&ctxh,  g_ctxh);
    cudaGetSymbolAddress((void**)&x1,    g_x1);
    cudaGetSymbolAddress((void**)&nx2h,  g_nx2h);
    cudaGetSymbolAddress((void**)&hh,    g_hh);
    cudaGetSymbolAddress((void**)&wqkvh, g_wqkvh);
    cudaGetSymbolAddress((void**)&bqkv,  g_bqkv);
    cudaGetSymbolAddress((void**)&woh,   g_woh);
    cudaGetSymbolAddress((void**)&w1h,   g_w1h);
    cudaGetSymbolAddress((void**)&w2h,   g_w2h);

    cudaFuncSetAttribute(gemm_f16<EPI_H16>,
                         cudaFuncAttributeMaxDynamicSharedMemorySize, GEMM_SMEM);
    cudaFuncSetAttribute(gemm_f16<EPI_RES>,
                         cudaFuncAttributeMaxDynamicSharedMemorySize, GEMM_SMEM);
    cudaFuncSetAttribute(gemm_f16<EPI_G16>,
                         cudaFuncAttributeMaxDynamicSharedMemorySize, GEMM_SMEM);

    cvt_all_kernel<<<CVT_TOTAL / 256, 256>>>(Wq, Wk, Wv, Wo, W1, W2,
                                             wqkvh, woh, w1h, w2h);
    pack_bias_kernel<<<(D_ + 255) / 256, 256>>>(bq, bk, bv, bqkv);
    ln_kernel<<<ROWS, 256>>>(x, ga, ba, nxh);

    dim3 gqkv(QKV_S / 128, ROWS / 128);
    gemm_f16<EPI_H16><<<gqkv, 128, GEMM_SMEM>>>(ROWS, QKV_S, D_, nxh, wqkvh,
                                                bqkv, nullptr, qkvh);

    attn_mma<<<dim3(S_ / 128, H_, B_), 256>>>(qkvh, mask, ctxh);

    dim3 g1(D_ / 128, ROWS / 128);
    gemm_f16<EPI_RES><<<g1, 128, GEMM_SMEM>>>(ROWS, D_, D_, ctxh, woh, bo, x, x1);

    ln_kernel<<<ROWS, 256>>>(x1, gf, bf, nx2h);

    dim3 g2(DFF_ / 128, ROWS / 128);
    gemm_f16<EPI_G16><<<g2, 128, GEMM_SMEM>>>(ROWS, DFF_, D_, nx2h, w1h, b1,
                                              nullptr, hh);

    gemm_f16<EPI_RES><<<g1, 128, GEMM_SMEM>>>(ROWS, D_, DFF_, hh, w2h, b2, x1, out);
}

// round 12
// speedup vs baseline: 2.1162x; 1.0114x over previous
#include <cuda_runtime.h>
#include <cuda_fp16.h>
#include <cstdint>

#define B_   2
#define S_   2048
#define D_   1024
#define H_   16
#define DK_  64
#define DFF_ 4096
#define ROWS (B_*S_)     // 4096
#define QKV_S (3*D_)     // 3072

// ---------------- scratch (device globals; no allocations allowed) ----------
__device__ __half g_nxh [ROWS*D_];      // LN1 out
__device__ __half g_qkvh[ROWS*QKV_S];   // packed q|k|v
__device__ __half g_ctxh[ROWS*D_];      // attention context
__device__ float  g_x1  [ROWS*D_];      // x after attn residual (fp32)
__device__ __half g_nx2h[ROWS*D_];      // LN2 out
__device__ __half g_hh  [ROWS*DFF_];    // ffn hidden
// fp16 weights
__device__ __half g_wqkvh[3*D_*D_];
__device__ float  g_bqkv[3*D_];
__device__ __half g_woh[D_*D_];
__device__ __half g_w1h[DFF_*D_], g_w2h[D_*DFF_];

// ---------------- helpers ----------------------------------------------------
__device__ __forceinline__ uint32_t smem_u32(const void* p) {
    uint32_t a;
    asm("{ .reg .u64 t; cvta.to.shared.u64 t, %1; cvt.u32.u64 %0, t; }"
        : "=r"(a) : "l"(p));
    return a;
}
__device__ __forceinline__ void cp16(uint32_t dst, const void* src) {
    asm volatile("cp.async.cg.shared.global [%0], [%1], 16;"
                 :: "r"(dst), "l"(src) : "memory");
}
__device__ __forceinline__ void cp_commit() {
    asm volatile("cp.async.commit_group;" ::: "memory");
}
__device__ __forceinline__ void ldsm4(uint32_t* r, uint32_t addr) {
    asm volatile("ldmatrix.sync.aligned.m8n8.x4.shared.b16 {%0,%1,%2,%3}, [%4];"
                 : "=r"(r[0]), "=r"(r[1]), "=r"(r[2]), "=r"(r[3]) : "r"(addr));
}
__device__ __forceinline__ void ldsm4t(uint32_t* r, uint32_t addr) {
    asm volatile("ldmatrix.sync.aligned.m8n8.x4.trans.shared.b16 {%0,%1,%2,%3}, [%4];"
                 : "=r"(r[0]), "=r"(r[1]), "=r"(r[2]), "=r"(r[3]) : "r"(addr));
}
// m16n8k16 fp16, fp32 accumulate
__device__ __forceinline__ void mma16h(float* c, const uint32_t* a,
                                       uint32_t b0, uint32_t b1) {
    asm volatile(
        "mma.sync.aligned.m16n8k16.row.col.f32.f16.f16.f32 "
        "{%0,%1,%2,%3}, {%4,%5,%6,%7}, {%8,%9}, {%0,%1,%2,%3};"
        : "+f"(c[0]), "+f"(c[1]), "+f"(c[2]), "+f"(c[3])
        : "r"(a[0]), "r"(a[1]), "r"(a[2]), "r"(a[3]), "r"(b0), "r"(b1));
}
// pack two f32 -> f16x2 (lo = first arg)
__device__ __forceinline__ uint32_t f16pk(float lo, float hi) {
    uint32_t r;
    asm("cvt.rn.f16x2.f32 %0, %1, %2;" : "=r"(r) : "f"(hi), "f"(lo));
    return r;
}

// ---------------- fused weight conversion + bias pack (MLP=4) ----------------
#define NDD4 (D_*D_/4)
#define NDF4 (DFF_*D_/4)
#define CVT_F4   (4*NDD4 + 2*NDF4)   // weight float4 conversions
#define BIAS_F4  (3*D_/4)            // 768 fp32 float4 bias copies
#define CVT_UNITS (CVT_F4 + BIAS_F4)
#define CVT_GRID ((CVT_UNITS + 1023) / 1024)

__global__ __launch_bounds__(256) void cvt_all_kernel(
    const float* __restrict__ Wq, const float* __restrict__ Wk,
    const float* __restrict__ Wv, const float* __restrict__ Wo,
    const float* __restrict__ W1, const float* __restrict__ W2,
    const float* __restrict__ bq, const float* __restrict__ bk,
    const float* __restrict__ bv,
    __half* __restrict__ wqkv, __half* __restrict__ wo,
    __half* __restrict__ w1h, __half* __restrict__ w2h,
    float* __restrict__ bqkv)
{
    const int base = (blockIdx.x * 256 + threadIdx.x) * 4;
    #pragma unroll
    for (int p = 0; p < 4; p++) {
        const int i = base + p;
        if (i >= CVT_UNITS) break;
        if (i < CVT_F4) {
            const float4* src; __half* dst; int si, off;
            if (i < NDD4)             { src = (const float4*)Wq; si = i;               dst = wqkv; off = i; }
            else if (i < 2*NDD4)      { src = (const float4*)Wk; si = i - NDD4;        dst = wqkv; off = i; }
            else if (i < 3*NDD4)      { src = (const float4*)Wv; si = i - 2*NDD4;      dst = wqkv; off = i; }
            else if (i < 4*NDD4)      { src = (const float4*)Wo; si = i - 3*NDD4;      dst = wo;   off = si; }
            else if (i < 4*NDD4+NDF4) { src = (const float4*)W1; si = i - 4*NDD4;      dst = w1h;  off = si; }
            else                      { src = (const float4*)W2; si = i - 4*NDD4-NDF4; dst = w2h;  off = si; }
            float4 v = src[si];
            uint2 o;
            o.x = f16pk(v.x, v.y);
            o.y = f16pk(v.z, v.w);
            *(uint2*)&dst[(size_t)off * 4] = o;
        } else {
            const int j = i - CVT_F4;     // 0..767
            const float4* s; int sj;
            if (j < 256)      { s = (const float4*)bq; sj = j; }
            else if (j < 512) { s = (const float4*)bk; sj = j - 256; }
            else              { s = (const float4*)bv; sj = j - 512; }
            ((float4*)bqkv)[j] = s[sj];
        }
    }
}

// ---------------- LayerNorm (fp16 out) ----------------------------------------
__global__ __launch_bounds__(256) void ln_kernel(
    const float* __restrict__ x, const float* __restrict__ g,
    const float* __restrict__ bta, __half* __restrict__ out)
{
    const int row = blockIdx.x;
    const int t   = threadIdx.x;
    const float4* xr = (const float4*)(x + (size_t)row * D_);
    float4 v = xr[t];
    float s  = v.x + v.y + v.z + v.w;
    float s2 = v.x*v.x + v.y*v.y + v.z*v.z + v.w*v.w;
    #pragma unroll
    for (int o = 16; o > 0; o >>= 1) {
        s  += __shfl_xor_sync(0xffffffffu, s,  o);
        s2 += __shfl_xor_sync(0xffffffffu, s2, o);
    }
    __shared__ float rs[8], rs2[8];
    const int w = t >> 5;
    if ((t & 31) == 0) { rs[w] = s; rs2[w] = s2; }
    __syncthreads();
    s = 0.f; s2 = 0.f;
    #pragma unroll
    for (int i = 0; i < 8; i++) { s += rs[i]; s2 += rs2[i]; }
    const float mu   = s * (1.0f / D_);
    const float var  = s2 * (1.0f / D_) - mu * mu;
    const float rstd = rsqrtf(var + 1e-5f);
    float4 gg = ((const float4*)g)[t];
    float4 bb = ((const float4*)bta)[t];
    uint2 o;
    o.x = f16pk((v.x - mu) * rstd * gg.x + bb.x,
                (v.y - mu) * rstd * gg.y + bb.y);
    o.y = f16pk((v.z - mu) * rstd * gg.z + bb.z,
                (v.w - mu) * rstd * gg.w + bb.w);
    *(uint2*)(out + (size_t)row * D_ + t * 4) = o;
}

// ---------------- FP16 GEMM-NT: 4 warps, warp tile 64x64, K-tile 64 ----------
// cp.async issues for tile i+2 interleaved into the s-step loop.
enum { EPI_H16 = 0, EPI_RES = 1, EPI_G16 = 2 };
#define STAGES 3
#define STAGE_BYTES 32768
#define GEMM_SMEM (STAGES * STAGE_BYTES)   // 96 KB

template <int EPI>
__global__ __launch_bounds__(128, 2) void gemm_f16(
    int M, int N, int K,
    const __half* __restrict__ A, const __half* __restrict__ Bw,
    const float* __restrict__ bias, const float* __restrict__ resid,
    void* __restrict__ Cout)
{
    extern __shared__ float sm[];
    const int tid  = threadIdx.x;
    const int lane = tid & 31;
    const int wid  = tid >> 5;
    const int wm = wid & 1;
    const int wn = wid >> 1;
    const int brow = blockIdx.y * 128;
    const int bcol = blockIdx.x * 128;
    const int T = K >> 6;

    const uint32_t smb = smem_u32(sm);

    int am[8], akq[8];
    uint32_t adoff[8];
    #pragma unroll
    for (int p = 0; p < 8; p++) {
        const int c = tid + 128 * p;
        am[p]  = c >> 3;
        akq[p] = c & 7;
        adoff[p] = (uint32_t)(am[p] * 128 + (((akq[p] ^ (am[p] & 7)) << 4)));
    }

    float acc[4][8][4];
    #pragma unroll
    for (int mi = 0; mi < 4; mi++)
        #pragma unroll
        for (int ni = 0; ni < 8; ni++)
            #pragma unroll
            for (int e = 0; e < 4; e++) acc[mi][ni][e] = 0.f;

    auto issue_full = [&](int i, int stg) {
        const uint32_t dA = smb + (uint32_t)stg * STAGE_BYTES;
        const uint32_t dB = dA + 16384u;
        const int kbase = i * 64;
        #pragma unroll
        for (int p = 0; p < 8; p++) {
            cp16(dA + adoff[p], A  + (size_t)(brow + am[p]) * K + kbase + akq[p] * 8);
            cp16(dB + adoff[p], Bw + (size_t)(bcol + am[p]) * K + kbase + akq[p] * 8);
        }
        cp_commit();
    };

    const int a_r  = lane & 15;
    const int a_kq = lane >> 4;
    const int b_r  = (lane & 7) + ((lane >> 4) << 3);
    const int b_kq = (lane >> 3) & 1;
    uint32_t abase[4], axor[4], bbase[4], bxor[4];
    #pragma unroll
    for (int mi = 0; mi < 4; mi++) {
        const int row = wm * 64 + mi * 16 + a_r;
        abase[mi] = (uint32_t)(row * 128);
        axor[mi]  = (uint32_t)(row & 7);
    }
    #pragma unroll
    for (int g = 0; g < 4; g++) {
        const int row = wn * 64 + g * 16 + b_r;
        bbase[g] = (uint32_t)(16384 + row * 128);
        bxor[g]  = (uint32_t)(row & 7);
    }

    issue_full(0, 0);
    issue_full(1, 1);

    int stg = 0;
    for (int i = 0; i < T; i++) {
        if (i < T - 1) asm volatile("cp.async.wait_group 1;" ::: "memory");
        else           asm volatile("cp.async.wait_group 0;" ::: "memory");
        __syncthreads();

        const bool pf = (i + 2 < T);
        int nstg = stg + 2; if (nstg >= STAGES) nstg -= STAGES;
        const uint32_t dA2 = smb + (uint32_t)nstg * STAGE_BYTES;
        const uint32_t dB2 = dA2 + 16384u;
        const int kb2 = (i + 2) * 64;

        const uint32_t bufb = smb + (uint32_t)stg * STAGE_BYTES;

        #pragma unroll
        for (int s = 0; s < 4; s++) {
            // interleave 2 cp16 A/B pairs of tile i+2 per s-step
            if (pf) {
                #pragma unroll
                for (int q = 0; q < 2; q++) {
                    const int p = s * 2 + q;
                    cp16(dA2 + adoff[p],
                         A  + (size_t)(brow + am[p]) * K + kb2 + akq[p] * 8);
                    cp16(dB2 + adoff[p],
                         Bw + (size_t)(bcol + am[p]) * K + kb2 + akq[p] * 8);
                }
            }
            const uint32_t k0q = (uint32_t)(s * 2);
            uint32_t af[4][4], bfr[4][4];
            #pragma unroll
            for (int mi = 0; mi < 4; mi++)
                ldsm4(af[mi], bufb + abase[mi] + (((k0q + a_kq) ^ axor[mi]) << 4));
            #pragma unroll
            for (int g = 0; g < 4; g++)
                ldsm4(bfr[g], bufb + bbase[g] + (((k0q + b_kq) ^ bxor[g]) << 4));
            #pragma unroll
            for (int mi = 0; mi < 4; mi++)
                #pragma unroll
                for (int ni = 0; ni < 8; ni++)
                    mma16h(acc[mi][ni], af[mi],
                           bfr[ni >> 1][(ni & 1) * 2],
                           bfr[ni >> 1][(ni & 1) * 2 + 1]);
        }
        if (pf) cp_commit();
        if (++stg == STAGES) stg = 0;
    }

    #pragma unroll
    for (int mi = 0; mi < 4; mi++) {
        #pragma unroll
        for (int ni = 0; ni < 8; ni++) {
            const int r0  = brow + wm * 64 + mi * 16 + (lane >> 2);
            const int col = bcol + wn * 64 + ni * 8 + 2 * (lane & 3);
            const float b0 = bias[col], b1 = bias[col + 1];
            float v[4] = { acc[mi][ni][0] + b0, acc[mi][ni][1] + b1,
                           acc[mi][ni][2] + b0, acc[mi][ni][3] + b1 };
            if (EPI == EPI_RES) {
                float* C = (float*)Cout;
                const float2 x0 = *(const float2*)&resid[(size_t)r0 * N + col];
                const float2 x1 = *(const float2*)&resid[(size_t)(r0 + 8) * N + col];
                v[0] += x0.x; v[1] += x0.y; v[2] += x1.x; v[3] += x1.y;
                *(float2*)&C[(size_t)r0 * N + col]       = make_float2(v[0], v[1]);
                *(float2*)&C[(size_t)(r0 + 8) * N + col] = make_float2(v[2], v[3]);
            } else {
                if (EPI == EPI_G16) {
                    #pragma unroll
                    for (int e = 0; e < 4; e++)
                        v[e] = 0.5f * v[e] *
                               (1.0f + erff(v[e] * 0.70710678118654752f));
                }
                __half* C = (__half*)Cout;
                *(uint32_t*)&C[(size_t)r0 * N + col]       = f16pk(v[0], v[1]);
                *(uint32_t*)&C[(size_t)(r0 + 8) * N + col] = f16pk(v[2], v[3]);
            }
        }
    }
}

// ---------------- fp16 flash attention: cp.async + ldmatrix(+trans) ----------
#define ATT_ROWB 144             // 72 halves per row
#define ATT_BUFB (64 * ATT_ROWB) // 9216 bytes per matrix per stage

__global__ __launch_bounds__(256) void attn_mma(
    const __half* __restrict__ QKV, const int* __restrict__ mask,
    __half* __restrict__ O)
{
    __shared__ __align__(16) __half Ks[2][64][72];   // [buf][key][dk]
    __shared__ __align__(16) __half Vs[2][64][72];   // [buf][key][dk]

    const int b = blockIdx.z, h = blockIdx.y;
    const int tid = threadIdx.x, lane = tid & 31, wid = tid >> 5;
    const int gp = lane >> 2, tg = lane & 3;
    const int qrow0 = blockIdx.x * 128 + wid * 16 + gp;

    const __half* Qb = QKV + (size_t)(b * S_) * QKV_S + h * DK_;
    const __half* Kb = Qb + D_;
    const __half* Vb = Qb + 2 * D_;

    const uint32_t ksb = smem_u32(&Ks[0][0][0]);
    const uint32_t vsb = smem_u32(&Vs[0][0][0]);

    int ckey[2], cch[2];
    #pragma unroll
    for (int p = 0; p < 2; p++) {
        const int c = tid + 256 * p;
        ckey[p] = c >> 3; cch[p] = c & 7;
    }
    auto issue_kv = [&](int kt, int buf) {
        const uint32_t kb = ksb + (uint32_t)buf * ATT_BUFB;
        const uint32_t vb = vsb + (uint32_t)buf * ATT_BUFB;
        #pragma unroll
        for (int p = 0; p < 2; p++) {
            const size_t g = (size_t)(kt + ckey[p]) * QKV_S + cch[p] * 8;
            const uint32_t off = (uint32_t)(ckey[p] * ATT_ROWB + cch[p] * 16);
            cp16(kb + off, Kb + g);
            cp16(vb + off, Vb + g);
        }
        cp_commit();
    };

    const uint32_t kcon = (uint32_t)(((((lane >> 4) & 1) * 8 + (lane & 7)) * ATT_ROWB)
                                     + (((lane >> 3) & 1) * 8) * 2);
    const uint32_t vcon = (uint32_t)((((lane >> 3) & 1) * 8 + (lane & 7)) * ATT_ROWB
                                     + (((lane >> 4) & 1) * 8) * 2);

    // Q fragments with 1/8 folded in (fp16 0.125 = 0x3000, exact power of 2)
    uint32_t qf[4][4];
    {
        const __half* q0p = Qb + (size_t)qrow0 * QKV_S;
        const __half* q1p = q0p + (size_t)8 * QKV_S;
        const uint32_t s125 = 0x30003000u;
        #pragma unroll
        for (int s = 0; s < 4; s++) {
            qf[s][0] = *(const uint32_t*)&q0p[16*s + 2*tg];
            qf[s][1] = *(const uint32_t*)&q1p[16*s + 2*tg];
            qf[s][2] = *(const uint32_t*)&q0p[16*s + 2*tg + 8];
            qf[s][3] = *(const uint32_t*)&q1p[16*s + 2*tg + 8];
            #pragma unroll
            for (int e = 0; e < 4; e++)
                asm("mul.rn.f16x2 %0, %0, %1;" : "+r"(qf[s][e]) : "r"(s125));
        }
    }

    float oa[8][4];
    #pragma unroll
    for (int j = 0; j < 8; j++)
        #pragma unroll
        for (int e = 0; e < 4; e++) oa[j][e] = 0.f;
    float m0c = -1e30f, m1c = -1e30f, l0 = 0.f, l1 = 0.f;

    const int* mr0 = mask + ((size_t)(b * S_ + qrow0)) * S_;
    const int* mr1 = mr0 + (size_t)8 * S_;

    issue_kv(0, 0);

    for (int it = 0; it < S_ / 64; it++) {
        asm volatile("cp.async.wait_group 0;" ::: "memory");
        __syncthreads();
        if (it + 1 < S_ / 64) issue_kv((it + 1) * 64, (it + 1) & 1);

        const uint32_t kbuf = ksb + (uint32_t)(it & 1) * ATT_BUFB;
        const uint32_t vbuf = vsb + (uint32_t)(it & 1) * ATT_BUFB;
        const int kt = it * 64;

        // S = (Q/8)·K^T
        float sc[8][4];
        #pragma unroll
        for (int j = 0; j < 8; j++)
            #pragma unroll
            for (int e = 0; e < 4; e++) sc[j][e] = 0.f;
        #pragma unroll
        for (int s = 0; s < 4; s++) {
            #pragma unroll
            for (int jj = 0; jj < 4; jj++) {
                uint32_t kf[4];
                ldsm4(kf, kbuf + (uint32_t)(jj * 2 * 8 * ATT_ROWB + s * 32) + kcon);
                mma16h(sc[2*jj],     qf[s], kf[0], kf[1]);
                mma16h(sc[2*jj + 1], qf[s], kf[2], kf[3]);
            }
        }

        // mask (scale already folded into Q)
        #pragma unroll
        for (int j = 0; j < 8; j++) {
            const int2 mm0 = *(const int2*)&mr0[kt + 8*j + 2*tg];
            const int2 mm1 = *(const int2*)&mr1[kt + 8*j + 2*tg];
            if (mm0.x) sc[j][0] = -10000.0f;
            if (mm0.y) sc[j][1] = -10000.0f;
            if (mm1.x) sc[j][2] = -10000.0f;
            if (mm1.y) sc[j][3] = -10000.0f;
        }

        // online softmax
        float t0 = -1e30f, t1 = -1e30f;
        #pragma unroll
        for (int j = 0; j < 8; j++) {
            t0 = fmaxf(t0, fmaxf(sc[j][0], sc[j][1]));
            t1 = fmaxf(t1, fmaxf(sc[j][2], sc[j][3]));
        }
        t0 = fmaxf(t0, __shfl_xor_sync(0xffffffffu, t0, 1));
        t0 = fmaxf(t0, __shfl_xor_sync(0xffffffffu, t0, 2));
        t1 = fmaxf(t1, __shfl_xor_sync(0xffffffffu, t1, 1));
        t1 = fmaxf(t1, __shfl_xor_sync(0xffffffffu, t1, 2));
        const float mn0 = fmaxf(m0c, t0), mn1 = fmaxf(m1c, t1);
        const float cr0 = __expf(m0c - mn0), cr1 = __expf(m1c - mn1);
        float ps0 = 0.f, ps1 = 0.f;
        #pragma unroll
        for (int j = 0; j < 8; j++) {
            sc[j][0] = __expf(sc[j][0] - mn0); ps0 += sc[j][0];
            sc[j][1] = __expf(sc[j][1] - mn0); ps0 += sc[j][1];
            sc[j][2] = __expf(sc[j][2] - mn1); ps1 += sc[j][2];
            sc[j][3] = __expf(sc[j][3] - mn1); ps1 += sc[j][3];
        }
        ps0 += __shfl_xor_sync(0xffffffffu, ps0, 1);
        ps0 += __shfl_xor_sync(0xffffffffu, ps0, 2);
        ps1 += __shfl_xor_sync(0xffffffffu, ps1, 1);
        ps1 += __shfl_xor_sync(0xffffffffu, ps1, 2);
        l0 = l0 * cr0 + ps0; m0c = mn0;
        l1 = l1 * cr1 + ps1; m1c = mn1;
        #pragma unroll
        for (int j = 0; j < 8; j++) {
            oa[j][0] *= cr0; oa[j][1] *= cr0;
            oa[j][2] *= cr1; oa[j][3] *= cr1;
        }

        // P -> fp16 A fragments (layout identity)
        uint32_t pa[4][4];
        #pragma unroll
        for (int t = 0; t < 4; t++) {
            pa[t][0] = f16pk(sc[2*t][0],     sc[2*t][1]);
            pa[t][1] = f16pk(sc[2*t][2],     sc[2*t][3]);
            pa[t][2] = f16pk(sc[2*t + 1][0], sc[2*t + 1][1]);
            pa[t][3] = f16pk(sc[2*t + 1][2], sc[2*t + 1][3]);
        }

        // O += P·V via ldmatrix.trans fragments
        #pragma unroll
        for (int t = 0; t < 4; t++) {
            #pragma unroll
            for (int jj = 0; jj < 4; jj++) {
                uint32_t vf[4];
                ldsm4t(vf, vbuf + (uint32_t)(t * 16 * ATT_ROWB + jj * 2 * 16) + vcon);
                mma16h(oa[2*jj],     pa[t], vf[0], vf[1]);
                mma16h(oa[2*jj + 1], pa[t], vf[2], vf[3]);
            }
        }
    }

    const float inv0 = 1.0f / l0, inv1 = 1.0f / l1;
    __half* o0 = O + ((size_t)(b * S_ + qrow0)) * D_ + h * DK_;
    __half* o1 = o0 + (size_t)8 * D_;
    #pragma unroll
    for (int j = 0; j < 8; j++) {
        *(uint32_t*)&o0[8*j + 2*tg] = f16pk(oa[j][0] * inv0, oa[j][1] * inv0);
        *(uint32_t*)&o1[8*j + 2*tg] = f16pk(oa[j][2] * inv1, oa[j][3] * inv1);
    }
}

// ---------------- launcher ----------------------------------------------------
extern "C" void kernel_launch(void* const* d_in, const int* in_sizes, int n_in,
                              void* d_out, int out_size)
{
    const float* x  = (const float*)d_in[0];
    const int*   mask = (const int*)d_in[1];
    const float* Wq = (const float*)d_in[2];  const float* bq = (const float*)d_in[3];
    const float* Wk = (const float*)d_in[4];  const float* bk = (const float*)d_in[5];
    const float* Wv = (const float*)d_in[6];  const float* bv = (const float*)d_in[7];
    const float* Wo = (const float*)d_in[8];  const float* bo = (const float*)d_in[9];
    const float* W1 = (const float*)d_in[10]; const float* b1 = (const float*)d_in[11];
    const float* W2 = (const float*)d_in[12]; const float* b2 = (const float*)d_in[13];
    const float* ga = (const float*)d_in[14]; const float* ba = (const float*)d_in[15];
    const float* gf = (const float*)d_in[16]; const float* bf = (const float*)d_in[17];
    float* out = (float*)d_out;

    __half *nxh, *qkvh, *ctxh, *nx2h, *hh, *wqkvh, *woh, *w1h, *w2h;
    float *x1, *bqkv;
    cudaGetSymbolAddress((void**)&nxh,   g_nxh);
    cudaGetSymbolAddress((void**)&qkvh,  g_qkvh);
    cudaGetSymbolAddress((void**)&ctxh,  g_ctxh);
    cudaGetSymbolAddress((void**)&x1,    g_x1);
    cudaGetSymbolAddress((void**)&nx2h,  g_nx2h);
    cudaGetSymbolAddress((void**)&hh,    g_hh);
    cudaGetSymbolAddress((void**)&wqkvh, g_wqkvh);
    cudaGetSymbolAddress((void**)&bqkv,  g_bqkv);
    cudaGetSymbolAddress((void**)&woh,   g_woh);
    cudaGetSymbolAddress((void**)&w1h,   g_w1h);
    cudaGetSymbolAddress((void**)&w2h,   g_w2h);

    cudaFuncSetAttribute(gemm_f16<EPI_H16>,
                         cudaFuncAttributeMaxDynamicSharedMemorySize, GEMM_SMEM);
    cudaFuncSetAttribute(gemm_f16<EPI_RES>,
                         cudaFuncAttributeMaxDynamicSharedMemorySize, GEMM_SMEM);
    cudaFuncSetAttribute(gemm_f16<EPI_G16>,
                         cudaFuncAttributeMaxDynamicSharedMemorySize, GEMM_SMEM);

    cvt_all_kernel<<<CVT_GRID, 256>>>(Wq, Wk, Wv, Wo, W1, W2, bq, bk, bv,
                                      wqkvh, woh, w1h, w2h, bqkv);
    ln_kernel<<<ROWS, 256>>>(x, ga, ba, nxh);

    dim3 gqkv(QKV_S / 128, ROWS / 128);
    gemm_f16<EPI_H16><<<gqkv, 128, GEMM_SMEM>>>(ROWS, QKV_S, D_, nxh, wqkvh,
                                                bqkv, nullptr, qkvh);

    attn_mma<<<dim3(S_ / 128, H_, B_), 256>>>(qkvh, mask, ctxh);

    dim3 g1(D_ / 128, ROWS / 128);
    gemm_f16<EPI_RES><<<g1, 128, GEMM_SMEM>>>(ROWS, D_, D_, ctxh, woh, bo, x, x1);

    ln_kernel<<<ROWS, 256>>>(x1, gf, bf, nx2h);

    dim3 g2(DFF_ / 128, ROWS / 128);
    gemm_f16<EPI_G16><<<g2, 128, GEMM_SMEM>>>(ROWS, DFF_, D_, nx2h, w1h, b1,
                                              nullptr, hh);

    gemm_f16<EPI_RES><<<g1, 128, GEMM_SMEM>>>(ROWS, D_, DFF_, hh, w2h, b2, x1, out);
}